// round 1
// baseline (speedup 1.0000x reference)
#include <cuda_runtime.h>
#include <math.h>

#define HDIM 2048
#define SLEN 2048
#define NH 16
#define NKV 8
#define HD 128
#define IDIM 8192
#define QKV_N 4096

// ---------------- scratch (device globals; no allocation) ----------------
__device__ float g_xnorm[(size_t)SLEN * HDIM];
__device__ float g_qkv  [(size_t)SLEN * QKV_N];
__device__ float g_attn [(size_t)SLEN * HDIM];
__device__ float g_hid  [(size_t)SLEN * HDIM];
__device__ float g_gu   [(size_t)SLEN * 2 * IDIM];
__device__ float g_h1   [(size_t)SLEN * IDIM];

// ---------------- RMSNorm: one block per row ----------------
__global__ void rmsnorm_kernel(const float* __restrict__ x, const float* __restrict__ w,
                               float* __restrict__ y) {
    int s = blockIdx.x;
    int tid = threadIdx.x;          // 256 threads
    const float4* xr = (const float4*)(x + (size_t)s * HDIM);
    const float4* wr = (const float4*)w;
    float4 v0 = xr[tid];
    float4 v1 = xr[tid + 256];
    float ss = v0.x*v0.x + v0.y*v0.y + v0.z*v0.z + v0.w*v0.w
             + v1.x*v1.x + v1.y*v1.y + v1.z*v1.z + v1.w*v1.w;
    __shared__ float red[8];
    #pragma unroll
    for (int o = 16; o; o >>= 1) ss += __shfl_xor_sync(0xffffffffu, ss, o);
    if ((tid & 31) == 0) red[tid >> 5] = ss;
    __syncthreads();
    if (tid < 8) {
        float t = red[tid];
        #pragma unroll
        for (int o = 4; o; o >>= 1) t += __shfl_xor_sync(0xffu, t, o);
        if (tid == 0) red[0] = t;
    }
    __syncthreads();
    float inv = rsqrtf(red[0] * (1.0f / HDIM) + 1e-6f);
    float4 w0 = wr[tid], w1 = wr[tid + 256];
    float4* yr = (float4*)(y + (size_t)s * HDIM);
    yr[tid]       = make_float4(v0.x*w0.x*inv, v0.y*w0.y*inv, v0.z*w0.z*inv, v0.w*w0.w*inv);
    yr[tid + 256] = make_float4(v1.x*w0.x*0.f + v1.x*w1.x*inv, v1.y*w1.y*inv, v1.z*w1.z*inv, v1.w*w1.w*inv);
}

// ---------------- SGEMM NT: C[M,N] = A[M,K] * B[N,K]^T (+resid) ----------------
// BM=BN=128, BK=16, 256 threads, 8x8 per thread.
__global__ __launch_bounds__(256, 2)
void sgemm_nt(const float* __restrict__ A, const float* __restrict__ B,
              const float* __restrict__ resid, float* __restrict__ C,
              int M, int N, int K) {
    __shared__ float As[16][128];
    __shared__ float Bs[16][128];
    int tid = threadIdx.x;
    int bn = blockIdx.x, bm = blockIdx.y;
    const float* Ab = A + (size_t)bm * 128 * K;
    const float* Bb = B + (size_t)bn * 128 * K;
    int lr = tid >> 2;            // 0..63
    int lc = (tid & 3) << 2;      // 0,4,8,12
    int tx = tid & 15, ty = tid >> 4;
    float acc[8][8];
    #pragma unroll
    for (int i = 0; i < 8; i++)
        #pragma unroll
        for (int j = 0; j < 8; j++) acc[i][j] = 0.f;

    for (int k0 = 0; k0 < K; k0 += 16) {
        #pragma unroll
        for (int i = 0; i < 2; i++) {
            int rr = lr + i * 64;
            float4 a = *(const float4*)(Ab + (size_t)rr * K + k0 + lc);
            As[lc + 0][rr] = a.x; As[lc + 1][rr] = a.y;
            As[lc + 2][rr] = a.z; As[lc + 3][rr] = a.w;
            float4 b = *(const float4*)(Bb + (size_t)rr * K + k0 + lc);
            Bs[lc + 0][rr] = b.x; Bs[lc + 1][rr] = b.y;
            Bs[lc + 2][rr] = b.z; Bs[lc + 3][rr] = b.w;
        }
        __syncthreads();
        #pragma unroll
        for (int k = 0; k < 16; k++) {
            float4 a0 = *(const float4*)&As[k][ty * 8];
            float4 a1 = *(const float4*)&As[k][ty * 8 + 4];
            float4 b0 = *(const float4*)&Bs[k][tx * 8];
            float4 b1 = *(const float4*)&Bs[k][tx * 8 + 4];
            float av[8] = {a0.x, a0.y, a0.z, a0.w, a1.x, a1.y, a1.z, a1.w};
            float bv[8] = {b0.x, b0.y, b0.z, b0.w, b1.x, b1.y, b1.z, b1.w};
            #pragma unroll
            for (int i = 0; i < 8; i++)
                #pragma unroll
                for (int j = 0; j < 8; j++)
                    acc[i][j] += av[i] * bv[j];
        }
        __syncthreads();
    }
    #pragma unroll
    for (int i = 0; i < 8; i++) {
        int row = bm * 128 + ty * 8 + i;
        size_t off = (size_t)row * N + bn * 128 + tx * 8;
        float4 o0 = make_float4(acc[i][0], acc[i][1], acc[i][2], acc[i][3]);
        float4 o1 = make_float4(acc[i][4], acc[i][5], acc[i][6], acc[i][7]);
        if (resid) {
            float4 r0 = *(const float4*)(resid + off);
            float4 r1 = *(const float4*)(resid + off + 4);
            o0.x += r0.x; o0.y += r0.y; o0.z += r0.z; o0.w += r0.w;
            o1.x += r1.x; o1.y += r1.y; o1.z += r1.z; o1.w += r1.w;
        }
        *(float4*)(C + off)     = o0;
        *(float4*)(C + off + 4) = o1;
    }
}

// ---------------- RoPE (in place on qkv) ----------------
__global__ void rope_kernel(float* __restrict__ qkv, const float* __restrict__ cs,
                            const float* __restrict__ sn) {
    int d = threadIdx.x;           // 0..63
    int hh = blockIdx.y;           // 0..23  (16 q heads + 8 kv heads)
    int s = blockIdx.x;
    int base = (hh < NH) ? hh * HD : HDIM + (hh - NH) * HD;
    float* p = qkv + (size_t)s * QKV_N + base;
    float x1 = p[d], x2 = p[d + 64];
    float c1 = cs[s * HD + d],      s1 = sn[s * HD + d];
    float c2 = cs[s * HD + d + 64], s2 = sn[s * HD + d + 64];
    p[d]      = x1 * c1 - x2 * s1;
    p[d + 64] = x2 * c2 + x1 * s2;
}

// ---------------- Flash attention (causal, GQA rep=2) ----------------
#define QKS 132          // padded row stride for Q/K/V tiles (floats)
#define PS  68           // padded row stride for P tile
#define ATT_SMEM ((3 * 64 * QKS + 64 * PS) * 4)

__global__ void attn_kernel(const float* __restrict__ qkv, float* __restrict__ out) {
    extern __shared__ float sm[];
    float* Qs = sm;
    float* Ks = Qs + 64 * QKS;
    float* Vs = Ks + 64 * QKS;
    float* Ps = Vs + 64 * QKS;
    int h = blockIdx.x;
    int qt = blockIdx.y;
    int tid = threadIdx.x;      // 256
    int r  = tid >> 2;          // row 0..63
    int c4 = tid & 3;
    int kv = h >> 1;
    const float scale = 0.08838834764831845f;   // 1/sqrt(128)

    // load Q tile (scaled)
    #pragma unroll
    for (int i = 0; i < 8; i++) {
        int idx = tid + i * 256;
        int row = idx >> 5, cc = idx & 31;
        float4 v = *(const float4*)(qkv + (size_t)(qt * 64 + row) * QKV_N + h * HD + cc * 4);
        v.x *= scale; v.y *= scale; v.z *= scale; v.w *= scale;
        *(float4*)(Qs + row * QKS + cc * 4) = v;
    }

    float m = -INFINITY, l = 0.f;
    float4 acc[8];
    #pragma unroll
    for (int q = 0; q < 8; q++) acc[q] = make_float4(0.f, 0.f, 0.f, 0.f);

    for (int kt = 0; kt <= qt; kt++) {
        __syncthreads();
        #pragma unroll
        for (int i = 0; i < 8; i++) {
            int idx = tid + i * 256;
            int row = idx >> 5, cc = idx & 31;
            size_t g = (size_t)(kt * 64 + row) * QKV_N + HDIM + kv * HD + cc * 4;
            *(float4*)(Ks + row * QKS + cc * 4) = *(const float4*)(qkv + g);
            *(float4*)(Vs + row * QKS + cc * 4) = *(const float4*)(qkv + g + NKV * HD);
        }
        __syncthreads();

        float s[16];
        #pragma unroll
        for (int cc = 0; cc < 16; cc++) s[cc] = 0.f;
        #pragma unroll 4
        for (int d4 = 0; d4 < 32; d4++) {
            float4 qv = *(const float4*)(Qs + r * QKS + d4 * 4);
            #pragma unroll
            for (int cc = 0; cc < 16; cc++) {
                float4 kvv = *(const float4*)(Ks + (c4 + 4 * cc) * QKS + d4 * 4);
                s[cc] += qv.x * kvv.x + qv.y * kvv.y + qv.z * kvv.z + qv.w * kvv.w;
            }
        }
        if (kt == qt) {
            #pragma unroll
            for (int cc = 0; cc < 16; cc++)
                if (c4 + 4 * cc > r) s[cc] = -INFINITY;
        }
        float tm = s[0];
        #pragma unroll
        for (int cc = 1; cc < 16; cc++) tm = fmaxf(tm, s[cc]);
        tm = fmaxf(tm, __shfl_xor_sync(0xffffffffu, tm, 1));
        tm = fmaxf(tm, __shfl_xor_sync(0xffffffffu, tm, 2));
        float mn = fmaxf(m, tm);
        float corr = __expf(m - mn);
        float ls = 0.f;
        #pragma unroll
        for (int cc = 0; cc < 16; cc++) {
            float p = __expf(s[cc] - mn);
            ls += p;
            Ps[r * PS + c4 + 4 * cc] = p;
        }
        ls += __shfl_xor_sync(0xffffffffu, ls, 1);
        ls += __shfl_xor_sync(0xffffffffu, ls, 2);
        l = l * corr + ls;
        m = mn;
        #pragma unroll
        for (int q = 0; q < 8; q++) {
            acc[q].x *= corr; acc[q].y *= corr; acc[q].z *= corr; acc[q].w *= corr;
        }
        __syncthreads();
        #pragma unroll 2
        for (int j = 0; j < 64; j++) {
            float p = Ps[r * PS + j];
            #pragma unroll
            for (int q = 0; q < 8; q++) {
                float4 v = *(const float4*)(Vs + j * QKS + c4 * 32 + q * 4);
                acc[q].x += p * v.x; acc[q].y += p * v.y;
                acc[q].z += p * v.z; acc[q].w += p * v.w;
            }
        }
    }
    float invl = 1.f / l;
    #pragma unroll
    for (int q = 0; q < 8; q++) {
        float4 o = make_float4(acc[q].x * invl, acc[q].y * invl, acc[q].z * invl, acc[q].w * invl);
        *(float4*)(out + (size_t)(qt * 64 + r) * HDIM + h * HD + c4 * 32 + q * 4) = o;
    }
}

// ---------------- SiLU(gate) * up ----------------
__global__ void silu_mul_kernel(const float* __restrict__ gu, float* __restrict__ o) {
    int idx = blockIdx.x * 256 + threadIdx.x;   // over SLEN*IDIM/4 float4
    int s = idx >> 11;       // /2048 float4 per row half
    int c = idx & 2047;
    const float4 u = *((const float4*)(gu + (size_t)s * 2 * IDIM) + c);
    const float4 g = *((const float4*)(gu + (size_t)s * 2 * IDIM + IDIM) + c);
    float4 r;
    r.x = u.x * (g.x / (1.f + __expf(-g.x)));
    r.y = u.y * (g.y / (1.f + __expf(-g.y)));
    r.z = u.z * (g.z / (1.f + __expf(-g.z)));
    r.w = u.w * (g.w / (1.f + __expf(-g.w)));
    *((float4*)(o + (size_t)s * IDIM) + c) = r;
}

// ---------------- launch ----------------
extern "C" void kernel_launch(void* const* d_in, const int* in_sizes, int n_in,
                              void* d_out, int out_size) {
    const float* hidden = (const float*)d_in[0];
    const float* wflat  = (const float*)d_in[1];
    const float* ln1    = (const float*)d_in[2];
    const float* ln2    = (const float*)d_in[3];
    const float* cosb   = (const float*)d_in[4];
    const float* sinb   = (const float*)d_in[5];
    float* out = (float*)d_out;

    float *xnorm, *qkv, *attn, *hid, *gu, *h1;
    cudaGetSymbolAddress((void**)&xnorm, g_xnorm);
    cudaGetSymbolAddress((void**)&qkv,   g_qkv);
    cudaGetSymbolAddress((void**)&attn,  g_attn);
    cudaGetSymbolAddress((void**)&hid,   g_hid);
    cudaGetSymbolAddress((void**)&gu,    g_gu);
    cudaGetSymbolAddress((void**)&h1,    g_h1);

    cudaFuncSetAttribute(attn_kernel, cudaFuncAttributeMaxDynamicSharedMemorySize, ATT_SMEM);

    // 1) input rmsnorm
    rmsnorm_kernel<<<SLEN, 256>>>(hidden, ln1, xnorm);
    // 2) fused QKV projection (q_w|k_w|v_w contiguous): [2048,4096]
    sgemm_nt<<<dim3(QKV_N / 128, SLEN / 128), 256>>>(xnorm, wflat, nullptr, qkv,
                                                     SLEN, QKV_N, HDIM);
    // 3) RoPE on q and k heads
    rope_kernel<<<dim3(SLEN, NH + NKV), 64>>>(qkv, cosb, sinb);
    // 4) causal attention
    attn_kernel<<<dim3(NH, SLEN / 64), 256, ATT_SMEM>>>(qkv, attn);
    // 5) o-projection + residual
    sgemm_nt<<<dim3(HDIM / 128, SLEN / 128), 256>>>(attn, wflat + 8388608, hidden, hid,
                                                    SLEN, HDIM, HDIM);
    // 6) post-attention rmsnorm
    rmsnorm_kernel<<<SLEN, 256>>>(hid, ln2, xnorm);
    // 7) fused up|gate projection: [2048,16384]
    sgemm_nt<<<dim3(2 * IDIM / 128, SLEN / 128), 256>>>(xnorm, wflat + 12582912, nullptr, gu,
                                                        SLEN, 2 * IDIM, HDIM);
    // 8) silu(gate)*up
    silu_mul_kernel<<<(SLEN * IDIM / 4) / 256, 256>>>(gu, h1);
    // 9) down projection + residual -> output
    sgemm_nt<<<dim3(HDIM / 128, SLEN / 128), 256>>>(h1, wflat + 46137344, hid, out,
                                                    SLEN, HDIM, IDIM);
}

// round 3
// speedup vs baseline: 1.9087x; 1.9087x over previous
#include <cuda_runtime.h>
#include <math.h>
#include <stdint.h>

#define HDIM 2048
#define SLEN 2048
#define NH 16
#define NKV 8
#define HD 128
#define IDIM 8192
#define QKV_N 4096
#define WTOTAL 62914560

// ---------------- scratch (device globals; no allocation) ----------------
__device__ float g_xnorm[(size_t)SLEN * HDIM];
__device__ float g_qkv  [(size_t)SLEN * QKV_N];
__device__ float g_attn [(size_t)SLEN * HDIM];
__device__ float g_hid  [(size_t)SLEN * HDIM];
__device__ float g_gu   [(size_t)SLEN * 2 * IDIM];
__device__ float g_h1   [(size_t)SLEN * IDIM];
__device__ float g_wtf  [(size_t)WTOTAL];      // tf32-rounded weights

// ---------------- helpers ----------------
__device__ __forceinline__ uint32_t smem_to_u32(const void* p) {
    uint32_t a;
    asm("{ .reg .u64 t; cvta.to.shared.u64 t, %1; cvt.u32.u64 %0, t; }" : "=r"(a) : "l"(p));
    return a;
}
__device__ __forceinline__ float tf32r(float x) {
    uint32_t u;
    asm("cvt.rna.tf32.f32 %0, %1;" : "=r"(u) : "f"(x));
    return __uint_as_float(u);
}
#define CP_ASYNC16(s, g) asm volatile("cp.async.cg.shared.global [%0], [%1], 16;" :: "r"(s), "l"(g))
#define CP_COMMIT() asm volatile("cp.async.commit_group;" ::: "memory")
#define CP_WAIT0() asm volatile("cp.async.wait_group 0;" ::: "memory")

// mma.sync m16n8k8 tf32: D += A*B  (A row-major frag, B col-major frag)
__device__ __forceinline__ void mma_tf32(float* d, const uint32_t* a, const uint32_t* b) {
    asm volatile(
        "mma.sync.aligned.m16n8k8.row.col.f32.tf32.tf32.f32 "
        "{%0,%1,%2,%3},{%4,%5,%6,%7},{%8,%9},{%0,%1,%2,%3};"
        : "+f"(d[0]), "+f"(d[1]), "+f"(d[2]), "+f"(d[3])
        : "r"(a[0]), "r"(a[1]), "r"(a[2]), "r"(a[3]), "r"(b[0]), "r"(b[1]));
}

// ---------------- tf32 mma GEMM NT: C[M,N] = A[M,K] @ B[N,K]^T (+resid) ------
// BM=BN=128, BK=32, 256 threads (8 warps, 2x4), warp tile 64x32, double-buffer.
#define BM 128
#define BN 128
#define BK 32
#define TSTR 36                              // padded row stride (floats)
#define STAGE_F (BM * TSTR)                  // floats per A (or B) stage
#define GEMM_SMEM (4 * STAGE_F * 4)          // 2 stages x (A+B) = 73728 bytes

__device__ __forceinline__ void load_tile(const float* __restrict__ Ag,
                                          const float* __restrict__ Bg, int K,
                                          uint32_t sa, uint32_t sbm, int stage,
                                          int tid, int k0) {
    uint32_t ab = sa + stage * (2 * STAGE_F * 4);
    uint32_t bb = sbm + stage * (2 * STAGE_F * 4);
    #pragma unroll
    for (int i = 0; i < 4; i++) {
        int idx = tid + i * 256;
        int r = idx >> 3, c = idx & 7;               // 128 rows x 8 float4
        uint32_t off = (r * TSTR + c * 4) * 4;
        CP_ASYNC16(ab + off, Ag + (size_t)r * K + k0 + c * 4);
        CP_ASYNC16(bb + off, Bg + (size_t)r * K + k0 + c * 4);
    }
}

__global__ __launch_bounds__(256, 2)
void gemm_tf32(const float* __restrict__ A, const float* __restrict__ B,
               const float* __restrict__ resid, float* __restrict__ C,
               int M, int N, int K) {
    extern __shared__ float sm[];
    uint32_t s0 = smem_to_u32(sm);
    uint32_t sa = s0;                        // A stages
    uint32_t sbm = s0 + STAGE_F * 4;         // B stages
    const float* Asm = sm;                   // same memory, float view
    int tid = threadIdx.x;
    int warp = tid >> 5, lane = tid & 31;
    int wm = warp >> 2, wn = warp & 3;
    int g = lane >> 2, tg = lane & 3;        // groupID, threadID-in-group
    int bn = blockIdx.x, bm = blockIdx.y;

    const float* Ag = A + (size_t)bm * BM * K;
    const float* Bg = B + (size_t)bn * BN * K;
    int T = K / BK;

    float acc[4][4][4];
    #pragma unroll
    for (int mi = 0; mi < 4; mi++)
        #pragma unroll
        for (int ni = 0; ni < 4; ni++)
            #pragma unroll
            for (int r = 0; r < 4; r++) acc[mi][ni][r] = 0.f;

    load_tile(Ag, Bg, K, sa, sbm, 0, tid, 0);
    CP_COMMIT();

    for (int t = 0; t < T; t++) {
        CP_WAIT0();
        __syncthreads();
        if (t + 1 < T) {
            load_tile(Ag, Bg, K, sa, sbm, (t + 1) & 1, tid, (t + 1) * BK);
            CP_COMMIT();
        }
        const float* As = Asm + (t & 1) * (2 * STAGE_F);
        const float* Bs = As + STAGE_F;
        #pragma unroll
        for (int ks = 0; ks < 4; ks++) {
            int k0 = ks * 8;
            uint32_t a[4][4], b[4][2];
            #pragma unroll
            for (int mi = 0; mi < 4; mi++) {
                int r1 = wm * 64 + mi * 16 + g;
                a[mi][0] = __float_as_uint(As[r1 * TSTR + k0 + tg]);
                a[mi][1] = __float_as_uint(As[(r1 + 8) * TSTR + k0 + tg]);
                a[mi][2] = __float_as_uint(As[r1 * TSTR + k0 + tg + 4]);
                a[mi][3] = __float_as_uint(As[(r1 + 8) * TSTR + k0 + tg + 4]);
            }
            #pragma unroll
            for (int ni = 0; ni < 4; ni++) {
                int rn = wn * 32 + ni * 8 + g;
                b[ni][0] = __float_as_uint(Bs[rn * TSTR + k0 + tg]);
                b[ni][1] = __float_as_uint(Bs[rn * TSTR + k0 + tg + 4]);
            }
            #pragma unroll
            for (int mi = 0; mi < 4; mi++)
                #pragma unroll
                for (int ni = 0; ni < 4; ni++)
                    mma_tf32(acc[mi][ni], a[mi], b[ni]);
        }
        __syncthreads();
    }

    // epilogue: warp tile 64x32, thread owns 2x(1x2) per 16x8 mma tile
    #pragma unroll
    for (int mi = 0; mi < 4; mi++) {
        int r0 = bm * BM + wm * 64 + mi * 16 + g;
        #pragma unroll
        for (int ni = 0; ni < 4; ni++) {
            int c = bn * BN + wn * 32 + ni * 8 + tg * 2;
            size_t o0 = (size_t)r0 * N + c;
            size_t o1 = (size_t)(r0 + 8) * N + c;
            float2 v0 = make_float2(acc[mi][ni][0], acc[mi][ni][1]);
            float2 v1 = make_float2(acc[mi][ni][2], acc[mi][ni][3]);
            if (resid) {
                float2 q0 = *(const float2*)(resid + o0);
                float2 q1 = *(const float2*)(resid + o1);
                v0.x += q0.x; v0.y += q0.y;
                v1.x += q1.x; v1.y += q1.y;
            }
            *(float2*)(C + o0) = v0;
            *(float2*)(C + o1) = v1;
        }
    }
}

// ---------------- weight rounding to tf32 ----------------
__global__ void wconv_kernel(const float* __restrict__ w, float* __restrict__ o) {
    int i = blockIdx.x * 256 + threadIdx.x;
    float4 v = ((const float4*)w)[i];
    v.x = tf32r(v.x); v.y = tf32r(v.y); v.z = tf32r(v.z); v.w = tf32r(v.w);
    ((float4*)o)[i] = v;
}

// ---------------- RMSNorm (output tf32-rounded) ----------------
__global__ void rmsnorm_kernel(const float* __restrict__ x, const float* __restrict__ w,
                               float* __restrict__ y) {
    int s = blockIdx.x;
    int tid = threadIdx.x;          // 256 threads
    const float4* xr = (const float4*)(x + (size_t)s * HDIM);
    const float4* wr = (const float4*)w;
    float4 v0 = xr[tid];
    float4 v1 = xr[tid + 256];
    float ss = v0.x*v0.x + v0.y*v0.y + v0.z*v0.z + v0.w*v0.w
             + v1.x*v1.x + v1.y*v1.y + v1.z*v1.z + v1.w*v1.w;
    __shared__ float red[8];
    #pragma unroll
    for (int o = 16; o; o >>= 1) ss += __shfl_xor_sync(0xffffffffu, ss, o);
    if ((tid & 31) == 0) red[tid >> 5] = ss;
    __syncthreads();
    if (tid < 8) {
        float t = red[tid];
        #pragma unroll
        for (int o = 4; o; o >>= 1) t += __shfl_xor_sync(0xffu, t, o);
        if (tid == 0) red[0] = t;
    }
    __syncthreads();
    float inv = rsqrtf(red[0] * (1.0f / HDIM) + 1e-6f);
    float4 w0 = wr[tid], w1 = wr[tid + 256];
    float4* yr = (float4*)(y + (size_t)s * HDIM);
    yr[tid]       = make_float4(tf32r(v0.x*w0.x*inv), tf32r(v0.y*w0.y*inv),
                                tf32r(v0.z*w0.z*inv), tf32r(v0.w*w0.w*inv));
    yr[tid + 256] = make_float4(tf32r(v1.x*w1.x*inv), tf32r(v1.y*w1.y*inv),
                                tf32r(v1.z*w1.z*inv), tf32r(v1.w*w1.w*inv));
}

// ---------------- RoPE (in place on qkv) ----------------
__global__ void rope_kernel(float* __restrict__ qkv, const float* __restrict__ cs,
                            const float* __restrict__ sn) {
    int d = threadIdx.x;           // 0..63
    int hh = blockIdx.y;           // 0..23
    int s = blockIdx.x;
    int base = (hh < NH) ? hh * HD : HDIM + (hh - NH) * HD;
    float* p = qkv + (size_t)s * QKV_N + base;
    float x1 = p[d], x2 = p[d + 64];
    float c1 = cs[s * HD + d],      s1 = sn[s * HD + d];
    float c2 = cs[s * HD + d + 64], s2 = sn[s * HD + d + 64];
    p[d]      = x1 * c1 - x2 * s1;
    p[d + 64] = x2 * c2 + x1 * s2;
}

// ---------------- Flash attention (causal, GQA rep=2), fp32 ----------------
#define QKS 132
#define PS  68
#define ATT_SMEM ((3 * 64 * QKS + 64 * PS) * 4)

__global__ void attn_kernel(const float* __restrict__ qkv, float* __restrict__ out) {
    extern __shared__ float sm[];
    float* Qs = sm;
    float* Ks = Qs + 64 * QKS;
    float* Vs = Ks + 64 * QKS;
    float* Ps = Vs + 64 * QKS;
    int h = blockIdx.x;
    int qt = blockIdx.y;
    int tid = threadIdx.x;
    int r  = tid >> 2;
    int c4 = tid & 3;
    int kv = h >> 1;
    const float scale = 0.08838834764831845f;

    #pragma unroll
    for (int i = 0; i < 8; i++) {
        int idx = tid + i * 256;
        int row = idx >> 5, cc = idx & 31;
        float4 v = *(const float4*)(qkv + (size_t)(qt * 64 + row) * QKV_N + h * HD + cc * 4);
        v.x *= scale; v.y *= scale; v.z *= scale; v.w *= scale;
        *(float4*)(Qs + row * QKS + cc * 4) = v;
    }

    float m = -INFINITY, l = 0.f;
    float4 acc[8];
    #pragma unroll
    for (int q = 0; q < 8; q++) acc[q] = make_float4(0.f, 0.f, 0.f, 0.f);

    for (int kt = 0; kt <= qt; kt++) {
        __syncthreads();
        #pragma unroll
        for (int i = 0; i < 8; i++) {
            int idx = tid + i * 256;
            int row = idx >> 5, cc = idx & 31;
            size_t gg = (size_t)(kt * 64 + row) * QKV_N + HDIM + kv * HD + cc * 4;
            *(float4*)(Ks + row * QKS + cc * 4) = *(const float4*)(qkv + gg);
            *(float4*)(Vs + row * QKS + cc * 4) = *(const float4*)(qkv + gg + NKV * HD);
        }
        __syncthreads();

        float s[16];
        #pragma unroll
        for (int cc = 0; cc < 16; cc++) s[cc] = 0.f;
        #pragma unroll 4
        for (int d4 = 0; d4 < 32; d4++) {
            float4 qv = *(const float4*)(Qs + r * QKS + d4 * 4);
            #pragma unroll
            for (int cc = 0; cc < 16; cc++) {
                float4 kvv = *(const float4*)(Ks + (c4 + 4 * cc) * QKS + d4 * 4);
                s[cc] += qv.x * kvv.x + qv.y * kvv.y + qv.z * kvv.z + qv.w * kvv.w;
            }
        }
        if (kt == qt) {
            #pragma unroll
            for (int cc = 0; cc < 16; cc++)
                if (c4 + 4 * cc > r) s[cc] = -INFINITY;
        }
        float tm = s[0];
        #pragma unroll
        for (int cc = 1; cc < 16; cc++) tm = fmaxf(tm, s[cc]);
        tm = fmaxf(tm, __shfl_xor_sync(0xffffffffu, tm, 1));
        tm = fmaxf(tm, __shfl_xor_sync(0xffffffffu, tm, 2));
        float mn = fmaxf(m, tm);
        float corr = __expf(m - mn);
        float ls = 0.f;
        #pragma unroll
        for (int cc = 0; cc < 16; cc++) {
            float p = __expf(s[cc] - mn);
            ls += p;
            Ps[r * PS + c4 + 4 * cc] = p;
        }
        ls += __shfl_xor_sync(0xffffffffu, ls, 1);
        ls += __shfl_xor_sync(0xffffffffu, ls, 2);
        l = l * corr + ls;
        m = mn;
        #pragma unroll
        for (int q = 0; q < 8; q++) {
            acc[q].x *= corr; acc[q].y *= corr; acc[q].z *= corr; acc[q].w *= corr;
        }
        __syncthreads();
        #pragma unroll 2
        for (int j = 0; j < 64; j++) {
            float p = Ps[r * PS + j];
            #pragma unroll
            for (int q = 0; q < 8; q++) {
                float4 v = *(const float4*)(Vs + j * QKS + c4 * 32 + q * 4);
                acc[q].x += p * v.x; acc[q].y += p * v.y;
                acc[q].z += p * v.z; acc[q].w += p * v.w;
            }
        }
    }
    float invl = 1.f / l;
    #pragma unroll
    for (int q = 0; q < 8; q++) {
        float4 o = make_float4(tf32r(acc[q].x * invl), tf32r(acc[q].y * invl),
                               tf32r(acc[q].z * invl), tf32r(acc[q].w * invl));
        *(float4*)(out + (size_t)(qt * 64 + r) * HDIM + h * HD + c4 * 32 + q * 4) = o;
    }
}

// ---------------- SiLU(gate) * up (output tf32-rounded) ----------------
__global__ void silu_mul_kernel(const float* __restrict__ gu, float* __restrict__ o) {
    int idx = blockIdx.x * 256 + threadIdx.x;
    int s = idx >> 11;
    int c = idx & 2047;
    const float4 u = *((const float4*)(gu + (size_t)s * 2 * IDIM) + c);
    const float4 g = *((const float4*)(gu + (size_t)s * 2 * IDIM + IDIM) + c);
    float4 r;
    r.x = tf32r(u.x * (g.x / (1.f + __expf(-g.x))));
    r.y = tf32r(u.y * (g.y / (1.f + __expf(-g.y))));
    r.z = tf32r(u.z * (g.z / (1.f + __expf(-g.z))));
    r.w = tf32r(u.w * (g.w / (1.f + __expf(-g.w))));
    *((float4*)(o + (size_t)s * IDIM) + c) = r;
}

// ---------------- launch ----------------
extern "C" void kernel_launch(void* const* d_in, const int* in_sizes, int n_in,
                              void* d_out, int out_size) {
    const float* hidden = (const float*)d_in[0];
    const float* wflat  = (const float*)d_in[1];
    const float* ln1    = (const float*)d_in[2];
    const float* ln2    = (const float*)d_in[3];
    const float* cosb   = (const float*)d_in[4];
    const float* sinb   = (const float*)d_in[5];
    float* out = (float*)d_out;

    float *xnorm, *qkv, *attn, *hid, *gu, *h1, *wtf;
    cudaGetSymbolAddress((void**)&xnorm, g_xnorm);
    cudaGetSymbolAddress((void**)&qkv,   g_qkv);
    cudaGetSymbolAddress((void**)&attn,  g_attn);
    cudaGetSymbolAddress((void**)&hid,   g_hid);
    cudaGetSymbolAddress((void**)&gu,    g_gu);
    cudaGetSymbolAddress((void**)&h1,    g_h1);
    cudaGetSymbolAddress((void**)&wtf,   g_wtf);

    cudaFuncSetAttribute(attn_kernel, cudaFuncAttributeMaxDynamicSharedMemorySize, ATT_SMEM);
    cudaFuncSetAttribute(gemm_tf32, cudaFuncAttributeMaxDynamicSharedMemorySize, GEMM_SMEM);

    // 0) round weights to tf32 (60M floats)
    wconv_kernel<<<WTOTAL / 4 / 256, 256>>>(wflat, wtf);
    // 1) input rmsnorm (tf32-rounded out)
    rmsnorm_kernel<<<SLEN, 256>>>(hidden, ln1, xnorm);
    // 2) fused QKV projection: [2048, 4096]
    gemm_tf32<<<dim3(QKV_N / BN, SLEN / BM), 256, GEMM_SMEM>>>(xnorm, wtf, nullptr, qkv,
                                                               SLEN, QKV_N, HDIM);
    // 3) RoPE
    rope_kernel<<<dim3(SLEN, NH + NKV), 64>>>(qkv, cosb, sinb);
    // 4) causal attention (fp32, output tf32-rounded)
    attn_kernel<<<dim3(NH, SLEN / 64), 256, ATT_SMEM>>>(qkv, attn);
    // 5) o-projection + residual
    gemm_tf32<<<dim3(HDIM / BN, SLEN / BM), 256, GEMM_SMEM>>>(attn, wtf + 8388608, hidden, hid,
                                                              SLEN, HDIM, HDIM);
    // 6) post-attention rmsnorm
    rmsnorm_kernel<<<SLEN, 256>>>(hid, ln2, xnorm);
    // 7) fused up|gate projection: [2048, 16384]
    gemm_tf32<<<dim3(2 * IDIM / BN, SLEN / BM), 256, GEMM_SMEM>>>(xnorm, wtf + 12582912, nullptr,
                                                                  gu, SLEN, 2 * IDIM, HDIM);
    // 8) silu(gate)*up (tf32-rounded out)
    silu_mul_kernel<<<(SLEN * IDIM / 4) / 256, 256>>>(gu, h1);
    // 9) down projection + residual -> output
    gemm_tf32<<<dim3(HDIM / BN, SLEN / BM), 256, GEMM_SMEM>>>(h1, wtf + 46137344, hid, out,
                                                              SLEN, HDIM, IDIM);
}

// round 5
// speedup vs baseline: 2.3218x; 1.2165x over previous
#include <cuda_runtime.h>
#include <cuda_fp16.h>
#include <math.h>
#include <stdint.h>

#define HDIM 2048
#define SLEN 2048
#define NH 16
#define NKV 8
#define HD 128
#define IDIM 8192
#define QKV_N 4096
#define WTOTAL 62914560

// ---------------- scratch (device globals; no allocation) ----------------
__device__ __half g_wh   [(size_t)WTOTAL];           // fp16 weights
__device__ __half g_xh   [(size_t)SLEN * HDIM];      // normed activations (half)
__device__ float  g_qkv  [(size_t)SLEN * QKV_N];     // qkv fp32 (gemm out, rope in place)
__device__ __half g_attnh[(size_t)SLEN * HDIM];      // attention out (half)
__device__ float  g_hid  [(size_t)SLEN * HDIM];      // residual stream fp32
__device__ float  g_gu   [(size_t)SLEN * 2 * IDIM];  // up|gate fp32
__device__ __half g_h1h  [(size_t)SLEN * IDIM];      // silu out half

// ---------------- helpers ----------------
__device__ __forceinline__ uint32_t smem_to_u32(const void* p) {
    uint32_t a;
    asm("{ .reg .u64 t; cvta.to.shared.u64 t, %1; cvt.u32.u64 %0, t; }" : "=r"(a) : "l"(p));
    return a;
}
#define CP_ASYNC16(s, g) asm volatile("cp.async.cg.shared.global [%0], [%1], 16;" :: "r"(s), "l"(g))
#define CP_COMMIT() asm volatile("cp.async.commit_group;" ::: "memory")
#define CP_WAIT0() asm volatile("cp.async.wait_group 0;" ::: "memory")

// mma.sync m16n8k16 fp16 -> fp32
__device__ __forceinline__ void mma_f16(float* d, const uint32_t* a, const uint32_t* b) {
    asm volatile(
        "mma.sync.aligned.m16n8k16.row.col.f32.f16.f16.f32 "
        "{%0,%1,%2,%3},{%4,%5,%6,%7},{%8,%9},{%0,%1,%2,%3};"
        : "+f"(d[0]), "+f"(d[1]), "+f"(d[2]), "+f"(d[3])
        : "r"(a[0]), "r"(a[1]), "r"(a[2]), "r"(a[3]), "r"(b[0]), "r"(b[1]));
}

// ---------------- fp16 mma GEMM NT: C[M,N](f32) = A[M,K] @ B[N,K]^T (+resid) --
// BM=BN=128, BK=64 halves, 256 threads (8 warps 2x4), warp tile 64x32, 2-stage.
#define BM 128
#define BN 128
#define BK 64
#define SAW 36                                // smem row stride in 32-bit words
#define TILE_B (BM * SAW * 4)                 // 18432 bytes per tile
#define STAGE_B (2 * TILE_B)                  // A+B per stage
#define GEMM_SMEM (2 * STAGE_B)               // 73728

__device__ __forceinline__ void load_tile(const __half* __restrict__ Ag,
                                          const __half* __restrict__ Bg, int K,
                                          uint32_t base, int stage, int tid, int k0) {
    uint32_t ab = base + stage * STAGE_B;
    uint32_t bb = ab + TILE_B;
    #pragma unroll
    for (int i = 0; i < 4; i++) {
        int idx = tid + i * 256;
        int r = idx >> 3, c = idx & 7;        // 128 rows x 8 chunks(16B = 8 halves)
        uint32_t off = r * (SAW * 4) + c * 16;
        CP_ASYNC16(ab + off, Ag + (size_t)r * K + k0 + c * 8);
        CP_ASYNC16(bb + off, Bg + (size_t)r * K + k0 + c * 8);
    }
}

__global__ __launch_bounds__(256, 2)
void gemm_f16(const __half* __restrict__ A, const __half* __restrict__ B,
              const float* __restrict__ resid, float* __restrict__ C,
              int M, int N, int K) {
    extern __shared__ char smem[];
    uint32_t s0 = smem_to_u32(smem);
    const uint32_t* W = (const uint32_t*)smem;     // word view
    int tid = threadIdx.x;
    int warp = tid >> 5, lane = tid & 31;
    int wm = warp >> 2, wn = warp & 3;
    int g = lane >> 2, tg = lane & 3;
    int bn = blockIdx.x, bm = blockIdx.y;

    const __half* Ag = A + (size_t)bm * BM * K;
    const __half* Bg = B + (size_t)bn * BN * K;
    int T = K / BK;

    float acc[4][4][4];
    #pragma unroll
    for (int mi = 0; mi < 4; mi++)
        #pragma unroll
        for (int ni = 0; ni < 4; ni++)
            #pragma unroll
            for (int r = 0; r < 4; r++) acc[mi][ni][r] = 0.f;

    load_tile(Ag, Bg, K, s0, 0, tid, 0);
    CP_COMMIT();

    for (int t = 0; t < T; t++) {
        CP_WAIT0();
        __syncthreads();
        if (t + 1 < T) {
            load_tile(Ag, Bg, K, s0, (t + 1) & 1, tid, (t + 1) * BK);
            CP_COMMIT();
        }
        const uint32_t* As = W + (t & 1) * (STAGE_B / 4);
        const uint32_t* Bs = As + TILE_B / 4;
        #pragma unroll
        for (int ks = 0; ks < 4; ks++) {
            int k0 = ks * 8;                  // word offset (16 halves)
            uint32_t a[4][4], b[4][2];
            #pragma unroll
            for (int mi = 0; mi < 4; mi++) {
                int r1 = wm * 64 + mi * 16 + g;
                a[mi][0] = As[r1 * SAW + k0 + tg];
                a[mi][1] = As[(r1 + 8) * SAW + k0 + tg];
                a[mi][2] = As[r1 * SAW + k0 + tg + 4];
                a[mi][3] = As[(r1 + 8) * SAW + k0 + tg + 4];
            }
            #pragma unroll
            for (int ni = 0; ni < 4; ni++) {
                int rn = wn * 32 + ni * 8 + g;
                b[ni][0] = Bs[rn * SAW + k0 + tg];
                b[ni][1] = Bs[rn * SAW + k0 + tg + 4];
            }
            #pragma unroll
            for (int mi = 0; mi < 4; mi++)
                #pragma unroll
                for (int ni = 0; ni < 4; ni++)
                    mma_f16(acc[mi][ni], a[mi], b[ni]);
        }
        __syncthreads();
    }

    #pragma unroll
    for (int mi = 0; mi < 4; mi++) {
        int r0 = bm * BM + wm * 64 + mi * 16 + g;
        #pragma unroll
        for (int ni = 0; ni < 4; ni++) {
            int c = bn * BN + wn * 32 + ni * 8 + tg * 2;
            size_t o0 = (size_t)r0 * N + c;
            size_t o1 = (size_t)(r0 + 8) * N + c;
            float2 v0 = make_float2(acc[mi][ni][0], acc[mi][ni][1]);
            float2 v1 = make_float2(acc[mi][ni][2], acc[mi][ni][3]);
            if (resid) {
                float2 q0 = *(const float2*)(resid + o0);
                float2 q1 = *(const float2*)(resid + o1);
                v0.x += q0.x; v0.y += q0.y;
                v1.x += q1.x; v1.y += q1.y;
            }
            *(float2*)(C + o0) = v0;
            *(float2*)(C + o1) = v1;
        }
    }
}

// ---------------- weights fp32 -> fp16 ----------------
__global__ void wconv_kernel(const float* __restrict__ w, __half* __restrict__ o) {
    int i = blockIdx.x * 256 + threadIdx.x;          // over WTOTAL/4
    float4 v = ((const float4*)w)[i];
    __half2 h0 = __floats2half2_rn(v.x, v.y);
    __half2 h1 = __floats2half2_rn(v.z, v.w);
    uint2 pk = make_uint2(*(uint32_t*)&h0, *(uint32_t*)&h1);
    ((uint2*)o)[i] = pk;
}

// ---------------- RMSNorm (fp32 in, half out) ----------------
__global__ void rmsnorm_kernel(const float* __restrict__ x, const float* __restrict__ w,
                               __half* __restrict__ y) {
    int s = blockIdx.x;
    int tid = threadIdx.x;          // 256
    const float4* xr = (const float4*)(x + (size_t)s * HDIM);
    const float4* wr = (const float4*)w;
    float4 v0 = xr[tid];
    float4 v1 = xr[tid + 256];
    float ss = v0.x*v0.x + v0.y*v0.y + v0.z*v0.z + v0.w*v0.w
             + v1.x*v1.x + v1.y*v1.y + v1.z*v1.z + v1.w*v1.w;
    __shared__ float red[8];
    #pragma unroll
    for (int o = 16; o; o >>= 1) ss += __shfl_xor_sync(0xffffffffu, ss, o);
    if ((tid & 31) == 0) red[tid >> 5] = ss;
    __syncthreads();
    if (tid < 8) {
        float t = red[tid];
        #pragma unroll
        for (int o = 4; o; o >>= 1) t += __shfl_xor_sync(0xffu, t, o);
        if (tid == 0) red[0] = t;
    }
    __syncthreads();
    float inv = rsqrtf(red[0] * (1.0f / HDIM) + 1e-6f);
    float4 w0 = wr[tid], w1 = wr[tid + 256];
    uint2* yr = (uint2*)(y + (size_t)s * HDIM);
    __half2 a0 = __floats2half2_rn(v0.x*w0.x*inv, v0.y*w0.y*inv);
    __half2 a1 = __floats2half2_rn(v0.z*w0.z*inv, v0.w*w0.w*inv);
    __half2 b0 = __floats2half2_rn(v1.x*w1.x*inv, v1.y*w1.y*inv);
    __half2 b1 = __floats2half2_rn(v1.z*w1.z*inv, v1.w*w1.w*inv);
    yr[tid]       = make_uint2(*(uint32_t*)&a0, *(uint32_t*)&a1);
    yr[tid + 256] = make_uint2(*(uint32_t*)&b0, *(uint32_t*)&b1);
}

// ---------------- RoPE (in place on fp32 qkv) ----------------
__global__ void rope_kernel(float* __restrict__ qkv, const float* __restrict__ cs,
                            const float* __restrict__ sn) {
    int d = threadIdx.x;           // 0..63
    int hh = blockIdx.y;           // 0..23  (16 q heads + 8 kv heads)
    int s = blockIdx.x;
    int base = (hh < NH) ? hh * HD : HDIM + (hh - NH) * HD;
    float* p = qkv + (size_t)s * QKV_N + base;
    float x1 = p[d], x2 = p[d + 64];
    float c1 = cs[s * HD + d],      s1 = sn[s * HD + d];
    float c2 = cs[s * HD + d + 64], s2 = sn[s * HD + d + 64];
    p[d]      = x1 * c1 - x2 * s1;
    p[d + 64] = x2 * c2 + x1 * s2;
}

// ---------------- Flash attention (causal, GQA rep=2), fp32 scalar (proven) ---
#define QKS 132
#define PS  68
#define ATT_SMEM ((3 * 64 * QKS + 64 * PS) * 4)

__global__ void attn_kernel(const float* __restrict__ qkv, __half* __restrict__ outh) {
    extern __shared__ float sm[];
    float* Qs = sm;
    float* Ks = Qs + 64 * QKS;
    float* Vs = Ks + 64 * QKS;
    float* Ps = Vs + 64 * QKS;
    int h = blockIdx.x;
    int qt = blockIdx.y;
    int tid = threadIdx.x;
    int r  = tid >> 2;
    int c4 = tid & 3;
    int kv = h >> 1;
    const float scale = 0.08838834764831845f;

    #pragma unroll
    for (int i = 0; i < 8; i++) {
        int idx = tid + i * 256;
        int row = idx >> 5, cc = idx & 31;
        float4 v = *(const float4*)(qkv + (size_t)(qt * 64 + row) * QKV_N + h * HD + cc * 4);
        v.x *= scale; v.y *= scale; v.z *= scale; v.w *= scale;
        *(float4*)(Qs + row * QKS + cc * 4) = v;
    }

    float m = -INFINITY, l = 0.f;
    float4 acc[8];
    #pragma unroll
    for (int q = 0; q < 8; q++) acc[q] = make_float4(0.f, 0.f, 0.f, 0.f);

    for (int kt = 0; kt <= qt; kt++) {
        __syncthreads();
        #pragma unroll
        for (int i = 0; i < 8; i++) {
            int idx = tid + i * 256;
            int row = idx >> 5, cc = idx & 31;
            size_t gg = (size_t)(kt * 64 + row) * QKV_N + HDIM + kv * HD + cc * 4;
            *(float4*)(Ks + row * QKS + cc * 4) = *(const float4*)(qkv + gg);
            *(float4*)(Vs + row * QKS + cc * 4) = *(const float4*)(qkv + gg + NKV * HD);
        }
        __syncthreads();

        float s[16];
        #pragma unroll
        for (int cc = 0; cc < 16; cc++) s[cc] = 0.f;
        #pragma unroll 4
        for (int d4 = 0; d4 < 32; d4++) {
            float4 qv = *(const float4*)(Qs + r * QKS + d4 * 4);
            #pragma unroll
            for (int cc = 0; cc < 16; cc++) {
                float4 kvv = *(const float4*)(Ks + (c4 + 4 * cc) * QKS + d4 * 4);
                s[cc] += qv.x * kvv.x + qv.y * kvv.y + qv.z * kvv.z + qv.w * kvv.w;
            }
        }
        if (kt == qt) {
            #pragma unroll
            for (int cc = 0; cc < 16; cc++)
                if (c4 + 4 * cc > r) s[cc] = -INFINITY;
        }
        float tm = s[0];
        #pragma unroll
        for (int cc = 1; cc < 16; cc++) tm = fmaxf(tm, s[cc]);
        tm = fmaxf(tm, __shfl_xor_sync(0xffffffffu, tm, 1));
        tm = fmaxf(tm, __shfl_xor_sync(0xffffffffu, tm, 2));
        float mn = fmaxf(m, tm);
        float corr = __expf(m - mn);
        float ls = 0.f;
        #pragma unroll
        for (int cc = 0; cc < 16; cc++) {
            float p = __expf(s[cc] - mn);
            ls += p;
            Ps[r * PS + c4 + 4 * cc] = p;
        }
        ls += __shfl_xor_sync(0xffffffffu, ls, 1);
        ls += __shfl_xor_sync(0xffffffffu, ls, 2);
        l = l * corr + ls;
        m = mn;
        #pragma unroll
        for (int q = 0; q < 8; q++) {
            acc[q].x *= corr; acc[q].y *= corr; acc[q].z *= corr; acc[q].w *= corr;
        }
        __syncthreads();
        #pragma unroll 2
        for (int j = 0; j < 64; j++) {
            float p = Ps[r * PS + j];
            #pragma unroll
            for (int q = 0; q < 8; q++) {
                float4 v = *(const float4*)(Vs + j * QKS + c4 * 32 + q * 4);
                acc[q].x += p * v.x; acc[q].y += p * v.y;
                acc[q].z += p * v.z; acc[q].w += p * v.w;
            }
        }
    }
    float invl = 1.f / l;
    #pragma unroll
    for (int q = 0; q < 8; q++) {
        __half2 h0 = __floats2half2_rn(acc[q].x * invl, acc[q].y * invl);
        __half2 h1 = __floats2half2_rn(acc[q].z * invl, acc[q].w * invl);
        *(uint2*)(outh + (size_t)(qt * 64 + r) * HDIM + h * HD + c4 * 32 + q * 4) =
            make_uint2(*(uint32_t*)&h0, *(uint32_t*)&h1);
    }
}

// ---------------- SiLU(gate) * up (half out) ----------------
__global__ void silu_mul_kernel(const float* __restrict__ gu, __half* __restrict__ o) {
    int idx = blockIdx.x * 256 + threadIdx.x;
    int s = idx >> 11;
    int c = idx & 2047;
    const float4 u = *((const float4*)(gu + (size_t)s * 2 * IDIM) + c);
    const float4 g = *((const float4*)(gu + (size_t)s * 2 * IDIM + IDIM) + c);
    float r0 = u.x * (g.x / (1.f + __expf(-g.x)));
    float r1 = u.y * (g.y / (1.f + __expf(-g.y)));
    float r2 = u.z * (g.z / (1.f + __expf(-g.z)));
    float r3 = u.w * (g.w / (1.f + __expf(-g.w)));
    __half2 h0 = __floats2half2_rn(r0, r1);
    __half2 h1 = __floats2half2_rn(r2, r3);
    ((uint2*)(o + (size_t)s * IDIM))[c] = make_uint2(*(uint32_t*)&h0, *(uint32_t*)&h1);
}

// ---------------- launch ----------------
extern "C" void kernel_launch(void* const* d_in, const int* in_sizes, int n_in,
                              void* d_out, int out_size) {
    const float* hidden = (const float*)d_in[0];
    const float* wflat  = (const float*)d_in[1];
    const float* ln1    = (const float*)d_in[2];
    const float* ln2    = (const float*)d_in[3];
    const float* cosb   = (const float*)d_in[4];
    const float* sinb   = (const float*)d_in[5];
    float* out = (float*)d_out;

    __half *wh, *xh, *attnh, *h1h;
    float *qkv, *hid, *gu;
    cudaGetSymbolAddress((void**)&wh,    g_wh);
    cudaGetSymbolAddress((void**)&xh,    g_xh);
    cudaGetSymbolAddress((void**)&qkv,   g_qkv);
    cudaGetSymbolAddress((void**)&attnh, g_attnh);
    cudaGetSymbolAddress((void**)&hid,   g_hid);
    cudaGetSymbolAddress((void**)&gu,    g_gu);
    cudaGetSymbolAddress((void**)&h1h,   g_h1h);

    cudaFuncSetAttribute(gemm_f16, cudaFuncAttributeMaxDynamicSharedMemorySize, GEMM_SMEM);
    cudaFuncSetAttribute(attn_kernel, cudaFuncAttributeMaxDynamicSharedMemorySize, ATT_SMEM);

    // 0) weights fp32 -> fp16
    wconv_kernel<<<WTOTAL / 4 / 256, 256>>>(wflat, wh);
    // 1) input rmsnorm -> half
    rmsnorm_kernel<<<SLEN, 256>>>(hidden, ln1, xh);
    // 2) fused QKV projection: [2048, 4096] (fp32 out)
    gemm_f16<<<dim3(QKV_N / BN, SLEN / BM), 256, GEMM_SMEM>>>(xh, wh, nullptr, qkv,
                                                              SLEN, QKV_N, HDIM);
    // 3) RoPE in place (fp32)
    rope_kernel<<<dim3(SLEN, NH + NKV), 64>>>(qkv, cosb, sinb);
    // 4) causal attention (fp32 scalar, half out)
    attn_kernel<<<dim3(NH, SLEN / 64), 256, ATT_SMEM>>>(qkv, attnh);
    // 5) o-projection + residual
    gemm_f16<<<dim3(HDIM / BN, SLEN / BM), 256, GEMM_SMEM>>>(attnh, wh + 8388608, hidden, hid,
                                                             SLEN, HDIM, HDIM);
    // 6) post-attention rmsnorm -> half
    rmsnorm_kernel<<<SLEN, 256>>>(hid, ln2, xh);
    // 7) fused up|gate projection: [2048, 16384]
    gemm_f16<<<dim3(2 * IDIM / BN, SLEN / BM), 256, GEMM_SMEM>>>(xh, wh + 12582912, nullptr,
                                                                 gu, SLEN, 2 * IDIM, HDIM);
    // 8) silu(gate)*up -> half
    silu_mul_kernel<<<(SLEN * IDIM / 4) / 256, 256>>>(gu, h1h);
    // 9) down projection + residual -> output
    gemm_f16<<<dim3(HDIM / BN, SLEN / BM), 256, GEMM_SMEM>>>(h1h, wh + 46137344, hid, out,
                                                             SLEN, HDIM, IDIM);
}

// round 6
// speedup vs baseline: 8.5162x; 3.6679x over previous
#include <cuda_runtime.h>
#include <cuda_fp16.h>
#include <math.h>
#include <stdint.h>

#define HDIM 2048
#define SLEN 2048
#define NH 16
#define NKV 8
#define HD 128
#define IDIM 8192
#define QKV_N 4096
#define WTOTAL 62914560

// ---------------- scratch (device globals; no allocation) ----------------
__device__ __half g_wh   [(size_t)WTOTAL];           // fp16 weights
__device__ __half g_xh   [(size_t)SLEN * HDIM];      // normed activations (half)
__device__ float  g_qkv  [(size_t)SLEN * QKV_N];     // qkv fp32 (gemm out)
__device__ __half g_qkvh [(size_t)SLEN * QKV_N];     // qkv half (post-rope)
__device__ __half g_attnh[(size_t)SLEN * HDIM];      // attention out (half)
__device__ float  g_hid  [(size_t)SLEN * HDIM];      // residual stream fp32
__device__ float  g_gu   [(size_t)SLEN * 2 * IDIM];  // up|gate fp32
__device__ __half g_h1h  [(size_t)SLEN * IDIM];      // silu out half

// ---------------- helpers ----------------
__device__ __forceinline__ uint32_t smem_to_u32(const void* p) {
    uint32_t a;
    asm("{ .reg .u64 t; cvta.to.shared.u64 t, %1; cvt.u32.u64 %0, t; }" : "=r"(a) : "l"(p));
    return a;
}
#define CP_ASYNC16(s, g) asm volatile("cp.async.cg.shared.global [%0], [%1], 16;" :: "r"(s), "l"(g))
#define CP_COMMIT() asm volatile("cp.async.commit_group;" ::: "memory")
#define CP_WAIT1() asm volatile("cp.async.wait_group 1;" ::: "memory")

// mma.sync m16n8k16 fp16 -> fp32
__device__ __forceinline__ void mma_f16(float* d, const uint32_t* a, const uint32_t* b) {
    asm volatile(
        "mma.sync.aligned.m16n8k16.row.col.f32.f16.f16.f32 "
        "{%0,%1,%2,%3},{%4,%5,%6,%7},{%8,%9},{%0,%1,%2,%3};"
        : "+f"(d[0]), "+f"(d[1]), "+f"(d[2]), "+f"(d[3])
        : "r"(a[0]), "r"(a[1]), "r"(a[2]), "r"(a[3]), "r"(b[0]), "r"(b[1]));
}

// ---------------- fp16 mma GEMM NT: C[M,N](f32) = A[M,K] @ B[N,K]^T (+resid) --
// BM=BN=128, BK=64 halves, 256 threads (8 warps 2x4), warp tile 64x32, 3-stage.
#define BM 128
#define BN 128
#define BK 64
#define SAW 36                                // smem row stride in 32-bit words
#define TILE_B (BM * SAW * 4)                 // 18432 bytes per tile
#define STAGE_B (2 * TILE_B)                  // A+B per stage
#define GEMM_SMEM (3 * STAGE_B)               // 110592

__device__ __forceinline__ void load_tile(const __half* __restrict__ Ag,
                                          const __half* __restrict__ Bg, int K,
                                          uint32_t base, int stage, int tid, int k0) {
    uint32_t ab = base + stage * STAGE_B;
    uint32_t bb = ab + TILE_B;
    #pragma unroll
    for (int i = 0; i < 4; i++) {
        int idx = tid + i * 256;
        int r = idx >> 3, c = idx & 7;        // 128 rows x 8 chunks(16B = 8 halves)
        uint32_t off = r * (SAW * 4) + c * 16;
        CP_ASYNC16(ab + off, Ag + (size_t)r * K + k0 + c * 8);
        CP_ASYNC16(bb + off, Bg + (size_t)r * K + k0 + c * 8);
    }
}

__global__ __launch_bounds__(256, 2)
void gemm_f16(const __half* __restrict__ A, const __half* __restrict__ B,
              const float* __restrict__ resid, float* __restrict__ C,
              int M, int N, int K) {
    extern __shared__ char smem[];
    uint32_t s0 = smem_to_u32(smem);
    const uint32_t* W = (const uint32_t*)smem;     // word view
    int tid = threadIdx.x;
    int warp = tid >> 5, lane = tid & 31;
    int wm = warp >> 2, wn = warp & 3;
    int g = lane >> 2, tg = lane & 3;
    int bn = blockIdx.x, bm = blockIdx.y;

    const __half* Ag = A + (size_t)bm * BM * K;
    const __half* Bg = B + (size_t)bn * BN * K;
    int T = K / BK;

    float acc[4][4][4];
    #pragma unroll
    for (int mi = 0; mi < 4; mi++)
        #pragma unroll
        for (int ni = 0; ni < 4; ni++)
            #pragma unroll
            for (int r = 0; r < 4; r++) acc[mi][ni][r] = 0.f;

    load_tile(Ag, Bg, K, s0, 0, tid, 0);
    CP_COMMIT();
    load_tile(Ag, Bg, K, s0, 1, tid, BK);
    CP_COMMIT();

    for (int t = 0; t < T; t++) {
        CP_WAIT1();                            // stage t complete (2 groups in flight)
        __syncthreads();
        int tn = t + 2;
        if (tn < T) load_tile(Ag, Bg, K, s0, tn % 3, tid, tn * BK);
        CP_COMMIT();                           // always commit -> invariant: 2 pending
        const uint32_t* As = W + (t % 3) * (STAGE_B / 4);
        const uint32_t* Bs = As + TILE_B / 4;
        #pragma unroll
        for (int ks = 0; ks < 4; ks++) {
            int k0 = ks * 8;                  // word offset (16 halves)
            uint32_t a[4][4], b[4][2];
            #pragma unroll
            for (int mi = 0; mi < 4; mi++) {
                int r1 = wm * 64 + mi * 16 + g;
                a[mi][0] = As[r1 * SAW + k0 + tg];
                a[mi][1] = As[(r1 + 8) * SAW + k0 + tg];
                a[mi][2] = As[r1 * SAW + k0 + tg + 4];
                a[mi][3] = As[(r1 + 8) * SAW + k0 + tg + 4];
            }
            #pragma unroll
            for (int ni = 0; ni < 4; ni++) {
                int rn = wn * 32 + ni * 8 + g;
                b[ni][0] = Bs[rn * SAW + k0 + tg];
                b[ni][1] = Bs[rn * SAW + k0 + tg + 4];
            }
            #pragma unroll
            for (int mi = 0; mi < 4; mi++)
                #pragma unroll
                for (int ni = 0; ni < 4; ni++)
                    mma_f16(acc[mi][ni], a[mi], b[ni]);
        }
    }

    #pragma unroll
    for (int mi = 0; mi < 4; mi++) {
        int r0 = bm * BM + wm * 64 + mi * 16 + g;
        #pragma unroll
        for (int ni = 0; ni < 4; ni++) {
            int c = bn * BN + wn * 32 + ni * 8 + tg * 2;
            size_t o0 = (size_t)r0 * N + c;
            size_t o1 = (size_t)(r0 + 8) * N + c;
            float2 v0 = make_float2(acc[mi][ni][0], acc[mi][ni][1]);
            float2 v1 = make_float2(acc[mi][ni][2], acc[mi][ni][3]);
            if (resid) {
                float2 q0 = *(const float2*)(resid + o0);
                float2 q1 = *(const float2*)(resid + o1);
                v0.x += q0.x; v0.y += q0.y;
                v1.x += q1.x; v1.y += q1.y;
            }
            *(float2*)(C + o0) = v0;
            *(float2*)(C + o1) = v1;
        }
    }
}

// ---------------- weights fp32 -> fp16 ----------------
__global__ void wconv_kernel(const float* __restrict__ w, __half* __restrict__ o) {
    int i = blockIdx.x * 256 + threadIdx.x;          // over WTOTAL/4
    float4 v = ((const float4*)w)[i];
    __half2 h0 = __floats2half2_rn(v.x, v.y);
    __half2 h1 = __floats2half2_rn(v.z, v.w);
    ((uint2*)o)[i] = make_uint2(*(uint32_t*)&h0, *(uint32_t*)&h1);
}

// ---------------- RMSNorm (fp32 in, half out) ----------------
__global__ void rmsnorm_kernel(const float* __restrict__ x, const float* __restrict__ w,
                               __half* __restrict__ y) {
    int s = blockIdx.x;
    int tid = threadIdx.x;          // 256
    const float4* xr = (const float4*)(x + (size_t)s * HDIM);
    const float4* wr = (const float4*)w;
    float4 v0 = xr[tid];
    float4 v1 = xr[tid + 256];
    float ss = v0.x*v0.x + v0.y*v0.y + v0.z*v0.z + v0.w*v0.w
             + v1.x*v1.x + v1.y*v1.y + v1.z*v1.z + v1.w*v1.w;
    __shared__ float red[8];
    #pragma unroll
    for (int o = 16; o; o >>= 1) ss += __shfl_xor_sync(0xffffffffu, ss, o);
    if ((tid & 31) == 0) red[tid >> 5] = ss;
    __syncthreads();
    if (tid < 8) {
        float t = red[tid];
        #pragma unroll
        for (int o = 4; o; o >>= 1) t += __shfl_xor_sync(0xffu, t, o);
        if (tid == 0) red[0] = t;
    }
    __syncthreads();
    float inv = rsqrtf(red[0] * (1.0f / HDIM) + 1e-6f);
    float4 w0 = wr[tid], w1 = wr[tid + 256];
    uint2* yr = (uint2*)(y + (size_t)s * HDIM);
    __half2 a0 = __floats2half2_rn(v0.x*w0.x*inv, v0.y*w0.y*inv);
    __half2 a1 = __floats2half2_rn(v0.z*w0.z*inv, v0.w*w0.w*inv);
    __half2 b0 = __floats2half2_rn(v1.x*w1.x*inv, v1.y*w1.y*inv);
    __half2 b1 = __floats2half2_rn(v1.z*w1.z*inv, v1.w*w1.w*inv);
    yr[tid]       = make_uint2(*(uint32_t*)&a0, *(uint32_t*)&a1);
    yr[tid + 256] = make_uint2(*(uint32_t*)&b0, *(uint32_t*)&b1);
}

// ---------------- RoPE + fp32->fp16 convert ----------------
__global__ void rope_kernel(const float* __restrict__ qkv, __half* __restrict__ qkvh,
                            const float* __restrict__ cs, const float* __restrict__ sn) {
    int d = threadIdx.x;           // 0..63
    int hh = blockIdx.y;           // 0..31: q 0-15, k 16-23, v 24-31
    int s = blockIdx.x;
    if (hh < NH + NKV) {
        int base = (hh < NH) ? hh * HD : HDIM + (hh - NH) * HD;
        const float* p = qkv + (size_t)s * QKV_N + base;
        __half* o = qkvh + (size_t)s * QKV_N + base;
        float x1 = p[d], x2 = p[d + 64];
        float c1 = cs[s * HD + d],      s1 = sn[s * HD + d];
        float c2 = cs[s * HD + d + 64], s2 = sn[s * HD + d + 64];
        o[d]      = __float2half_rn(x1 * c1 - x2 * s1);
        o[d + 64] = __float2half_rn(x2 * c2 + x1 * s2);
    } else {
        int base = HDIM + NKV * HD + (hh - NH - NKV) * HD;
        const float* p = qkv + (size_t)s * QKV_N + base;
        __half* o = qkvh + (size_t)s * QKV_N + base;
        o[d]      = __float2half_rn(p[d]);
        o[d + 64] = __float2half_rn(p[d + 64]);
    }
}

// ---------------- Flash attention (causal, GQA rep=2), fp16 mma -------------
// CTA: (head, 128 q-rows). 8 warps x 16 rows (row-complete). K-tiles of 64.
// Strides: Q/K rows = 128 halves, padded stride 136 halves (68 words).
//          Vt rows = 64 halves (k-dim), padded stride 72 halves (36 words).
#define QSTRH 136
#define QSTRW 68
#define VSTRH 72
#define VSTRW 36
#define ATT_Q_H (128 * QSTRH)                 // halves
#define ATT_K_H (64 * QSTRH)
#define ATT_V_H (128 * VSTRH)
#define ATT_SMEM ((ATT_Q_H + ATT_K_H + ATT_V_H) * 2)   // 70656 bytes

__global__ __launch_bounds__(256)
void attn_f16(const __half* __restrict__ qkvh, __half* __restrict__ outh) {
    extern __shared__ __half ash[];
    __half* Qs = ash;
    __half* Ks = Qs + ATT_Q_H;
    __half* Vt = Ks + ATT_K_H;

    int bid = blockIdx.x;
    int h = bid & 15;
    int p = bid >> 4;
    int qt = (p < 8) ? (15 - p) : (p - 8);   // heavy tiles first
    int tid = threadIdx.x;
    int warp = tid >> 5, lane = tid & 31;
    int g = lane >> 2, tg = lane & 3;
    int kvh = h >> 1;
    const float scale = 0.08838834764831845f;   // 1/sqrt(128)

    const uint32_t* Qw = (const uint32_t*)Qs;
    const uint32_t* Kw = (const uint32_t*)Ks;
    const uint32_t* Vw = (const uint32_t*)Vt;

    // load Q tile: 128 rows x 16 chunks(8 halves)
    #pragma unroll
    for (int i = 0; i < 8; i++) {
        int idx = tid + i * 256;
        int r = idx >> 4, c = idx & 15;
        *(uint4*)(Qs + r * QSTRH + c * 8) =
            *(const uint4*)(qkvh + (size_t)(qt * 128 + r) * QKV_N + h * HD + c * 8);
    }

    float o[16][4];
    #pragma unroll
    for (int nt = 0; nt < 16; nt++)
        #pragma unroll
        for (int r = 0; r < 4; r++) o[nt][r] = 0.f;
    float m0 = -INFINITY, m1 = -INFINITY, l0 = 0.f, l1 = 0.f;

    int row0 = qt * 128 + warp * 16 + g;
    int row1 = row0 + 8;
    int rowA = (warp * 16 + g) * QSTRW + tg;     // word base for Q frags

    int nkt = 2 * qt + 2;
    for (int kt = 0; kt < nkt; kt++) {
        __syncthreads();
        // load K tile (64 x 128 halves)
        #pragma unroll
        for (int i = 0; i < 4; i++) {
            int idx = tid + i * 256;
            int r = idx >> 4, c = idx & 15;
            *(uint4*)(Ks + r * QSTRH + c * 8) =
                *(const uint4*)(qkvh + (size_t)(kt * 64 + r) * QKV_N + HDIM + kvh * HD + c * 8);
        }
        // load V transposed: Vt[n][k]; thread handles one n, 16 k-pairs
        {
            int n = tid & 127;
            int kw0 = (tid >> 7) * 16;
            const __half* vsrc = qkvh + (size_t)(kt * 64) * QKV_N + HDIM + NKV * HD + kvh * HD + n;
            #pragma unroll
            for (int wv = 0; wv < 16; wv++) {
                int k = (kw0 + wv) * 2;
                __half v0 = vsrc[(size_t)k * QKV_N];
                __half v1 = vsrc[(size_t)(k + 1) * QKV_N];
                *(__half2*)(Vt + n * VSTRH + k) = __halves2half2(v0, v1);
            }
        }
        __syncthreads();

        // S = Q @ K^T : warp computes 16x64
        float s[8][4];
        #pragma unroll
        for (int nt = 0; nt < 8; nt++)
            #pragma unroll
            for (int r = 0; r < 4; r++) s[nt][r] = 0.f;
        #pragma unroll
        for (int ks = 0; ks < 8; ks++) {
            int k0 = ks * 8;
            uint32_t a[4];
            a[0] = Qw[rowA + k0];
            a[1] = Qw[rowA + 8 * QSTRW + k0];
            a[2] = Qw[rowA + k0 + 4];
            a[3] = Qw[rowA + 8 * QSTRW + k0 + 4];
            #pragma unroll
            for (int nt = 0; nt < 8; nt++) {
                uint32_t b[2];
                int rn = (nt * 8 + g) * QSTRW + tg;
                b[0] = Kw[rn + k0];
                b[1] = Kw[rn + k0 + 4];
                mma_f16(s[nt], a, b);
            }
        }

        // softmax (fp32), causal mask on diagonal tiles
        bool diag = (kt >= 2 * qt);
        float tm0 = -INFINITY, tm1 = -INFINITY;
        #pragma unroll
        for (int nt = 0; nt < 8; nt++) {
            #pragma unroll
            for (int r = 0; r < 4; r++) s[nt][r] *= scale;
            if (diag) {
                int c0 = kt * 64 + nt * 8 + 2 * tg;
                if (c0 > row0)     s[nt][0] = -INFINITY;
                if (c0 + 1 > row0) s[nt][1] = -INFINITY;
                if (c0 > row1)     s[nt][2] = -INFINITY;
                if (c0 + 1 > row1) s[nt][3] = -INFINITY;
            }
            tm0 = fmaxf(tm0, fmaxf(s[nt][0], s[nt][1]));
            tm1 = fmaxf(tm1, fmaxf(s[nt][2], s[nt][3]));
        }
        tm0 = fmaxf(tm0, __shfl_xor_sync(0xffffffffu, tm0, 1));
        tm0 = fmaxf(tm0, __shfl_xor_sync(0xffffffffu, tm0, 2));
        tm1 = fmaxf(tm1, __shfl_xor_sync(0xffffffffu, tm1, 1));
        tm1 = fmaxf(tm1, __shfl_xor_sync(0xffffffffu, tm1, 2));
        float mn0 = fmaxf(m0, tm0), mn1 = fmaxf(m1, tm1);
        float corr0 = __expf(m0 - mn0), corr1 = __expf(m1 - mn1);

        uint32_t ph0[8], ph1[8];     // P fragments: row g pair, row g+8 pair
        float ls0 = 0.f, ls1 = 0.f;
        #pragma unroll
        for (int nt = 0; nt < 8; nt++) {
            float p00 = __expf(s[nt][0] - mn0);
            float p01 = __expf(s[nt][1] - mn0);
            float p10 = __expf(s[nt][2] - mn1);
            float p11 = __expf(s[nt][3] - mn1);
            ls0 += p00 + p01; ls1 += p10 + p11;
            __half2 h0 = __floats2half2_rn(p00, p01);
            __half2 h1 = __floats2half2_rn(p10, p11);
            ph0[nt] = *(uint32_t*)&h0;
            ph1[nt] = *(uint32_t*)&h1;
        }
        ls0 += __shfl_xor_sync(0xffffffffu, ls0, 1);
        ls0 += __shfl_xor_sync(0xffffffffu, ls0, 2);
        ls1 += __shfl_xor_sync(0xffffffffu, ls1, 1);
        ls1 += __shfl_xor_sync(0xffffffffu, ls1, 2);
        l0 = l0 * corr0 + ls0;
        l1 = l1 * corr1 + ls1;
        m0 = mn0; m1 = mn1;
        #pragma unroll
        for (int nt = 0; nt < 16; nt++) {
            o[nt][0] *= corr0; o[nt][1] *= corr0;
            o[nt][2] *= corr1; o[nt][3] *= corr1;
        }

        // O += P @ V : K-dim 64 -> 4 ksteps of 16; A frags from registers
        #pragma unroll
        for (int ks = 0; ks < 4; ks++) {
            uint32_t a[4];
            a[0] = ph0[2 * ks];
            a[1] = ph1[2 * ks];
            a[2] = ph0[2 * ks + 1];
            a[3] = ph1[2 * ks + 1];
            int k0 = ks * 8;
            #pragma unroll
            for (int nt = 0; nt < 16; nt++) {
                uint32_t b[2];
                int rn = (nt * 8 + g) * VSTRW + tg;
                b[0] = Vw[rn + k0];
                b[1] = Vw[rn + k0 + 4];
                mma_f16(o[nt], a, b);
            }
        }
    }

    float inv0 = 1.f / l0, inv1 = 1.f / l1;
    #pragma unroll
    for (int nt = 0; nt < 16; nt++) {
        int col = h * HD + nt * 8 + 2 * tg;
        __half2 w0 = __floats2half2_rn(o[nt][0] * inv0, o[nt][1] * inv0);
        __half2 w1 = __floats2half2_rn(o[nt][2] * inv1, o[nt][3] * inv1);
        *(__half2*)(outh + (size_t)row0 * HDIM + col) = w0;
        *(__half2*)(outh + (size_t)row1 * HDIM + col) = w1;
    }
}

// ---------------- SiLU(gate) * up (half out) ----------------
__global__ void silu_mul_kernel(const float* __restrict__ gu, __half* __restrict__ o) {
    int idx = blockIdx.x * 256 + threadIdx.x;
    int s = idx >> 11;
    int c = idx & 2047;
    const float4 u = *((const float4*)(gu + (size_t)s * 2 * IDIM) + c);
    const float4 g = *((const float4*)(gu + (size_t)s * 2 * IDIM + IDIM) + c);
    float r0 = u.x * (g.x / (1.f + __expf(-g.x)));
    float r1 = u.y * (g.y / (1.f + __expf(-g.y)));
    float r2 = u.z * (g.z / (1.f + __expf(-g.z)));
    float r3 = u.w * (g.w / (1.f + __expf(-g.w)));
    __half2 h0 = __floats2half2_rn(r0, r1);
    __half2 h1 = __floats2half2_rn(r2, r3);
    ((uint2*)(o + (size_t)s * IDIM))[c] = make_uint2(*(uint32_t*)&h0, *(uint32_t*)&h1);
}

// ---------------- launch ----------------
extern "C" void kernel_launch(void* const* d_in, const int* in_sizes, int n_in,
                              void* d_out, int out_size) {
    const float* hidden = (const float*)d_in[0];
    const float* wflat  = (const float*)d_in[1];
    const float* ln1    = (const float*)d_in[2];
    const float* ln2    = (const float*)d_in[3];
    const float* cosb   = (const float*)d_in[4];
    const float* sinb   = (const float*)d_in[5];
    float* out = (float*)d_out;

    __half *wh, *xh, *qkvh, *attnh, *h1h;
    float *qkv, *hid, *gu;
    cudaGetSymbolAddress((void**)&wh,    g_wh);
    cudaGetSymbolAddress((void**)&xh,    g_xh);
    cudaGetSymbolAddress((void**)&qkv,   g_qkv);
    cudaGetSymbolAddress((void**)&qkvh,  g_qkvh);
    cudaGetSymbolAddress((void**)&attnh, g_attnh);
    cudaGetSymbolAddress((void**)&hid,   g_hid);
    cudaGetSymbolAddress((void**)&gu,    g_gu);
    cudaGetSymbolAddress((void**)&h1h,   g_h1h);

    cudaFuncSetAttribute(gemm_f16, cudaFuncAttributeMaxDynamicSharedMemorySize, GEMM_SMEM);
    cudaFuncSetAttribute(attn_f16, cudaFuncAttributeMaxDynamicSharedMemorySize, ATT_SMEM);

    // 0) weights fp32 -> fp16
    wconv_kernel<<<WTOTAL / 4 / 256, 256>>>(wflat, wh);
    // 1) input rmsnorm -> half
    rmsnorm_kernel<<<SLEN, 256>>>(hidden, ln1, xh);
    // 2) fused QKV projection: [2048, 4096] (fp32 out)
    gemm_f16<<<dim3(QKV_N / BN, SLEN / BM), 256, GEMM_SMEM>>>(xh, wh, nullptr, qkv,
                                                              SLEN, QKV_N, HDIM);
    // 3) RoPE + half convert
    rope_kernel<<<dim3(SLEN, 32), 64>>>(qkv, qkvh, cosb, sinb);
    // 4) causal attention (fp16 mma, fp32 softmax)
    attn_f16<<<256, 256, ATT_SMEM>>>(qkvh, attnh);
    // 5) o-projection + residual
    gemm_f16<<<dim3(HDIM / BN, SLEN / BM), 256, GEMM_SMEM>>>(attnh, wh + 8388608, hidden, hid,
                                                             SLEN, HDIM, HDIM);
    // 6) post-attention rmsnorm -> half
    rmsnorm_kernel<<<SLEN, 256>>>(hid, ln2, xh);
    // 7) fused up|gate projection: [2048, 16384]
    gemm_f16<<<dim3(2 * IDIM / BN, SLEN / BM), 256, GEMM_SMEM>>>(xh, wh + 12582912, nullptr,
                                                                 gu, SLEN, 2 * IDIM, HDIM);
    // 8) silu(gate)*up -> half
    silu_mul_kernel<<<(SLEN * IDIM / 4) / 256, 256>>>(gu, h1h);
    // 9) down projection + residual -> output
    gemm_f16<<<dim3(HDIM / BN, SLEN / BM), 256, GEMM_SMEM>>>(h1h, wh + 46137344, hid, out,
                                                             SLEN, HDIM, IDIM);
}

// round 7
// speedup vs baseline: 8.6609x; 1.0170x over previous
#include <cuda_runtime.h>
#include <cuda_fp16.h>
#include <math.h>
#include <stdint.h>

#define HDIM 2048
#define SLEN 2048
#define NH 16
#define NKV 8
#define HD 128
#define IDIM 8192
#define QKV_N 4096
#define WTOTAL 62914560

// ---------------- scratch (device globals; no allocation) ----------------
__device__ __half g_wh   [(size_t)WTOTAL];           // fp16 weights
__device__ __half g_xh   [(size_t)SLEN * HDIM];      // normed activations (half)
__device__ __half g_qkvh [(size_t)SLEN * QKV_N];     // qkv half (rope in place)
__device__ __half g_attnh[(size_t)SLEN * HDIM];      // attention out (half)
__device__ float  g_hid  [(size_t)SLEN * HDIM];      // residual stream fp32
__device__ __half g_guh  [(size_t)SLEN * 2 * IDIM];  // up|gate half
__device__ __half g_h1h  [(size_t)SLEN * IDIM];      // silu out half

// ---------------- helpers ----------------
__device__ __forceinline__ uint32_t smem_to_u32(const void* p) {
    uint32_t a;
    asm("{ .reg .u64 t; cvta.to.shared.u64 t, %1; cvt.u32.u64 %0, t; }" : "=r"(a) : "l"(p));
    return a;
}
#define CP_ASYNC16(s, g) asm volatile("cp.async.cg.shared.global [%0], [%1], 16;" :: "r"(s), "l"(g))
#define CP_COMMIT() asm volatile("cp.async.commit_group;" ::: "memory")
#define CP_WAIT1() asm volatile("cp.async.wait_group 1;" ::: "memory")

#define LDSM_X4(r0, r1, r2, r3, addr) \
    asm volatile("ldmatrix.sync.aligned.m8n8.x4.shared.b16 {%0,%1,%2,%3}, [%4];" \
        : "=r"(r0), "=r"(r1), "=r"(r2), "=r"(r3) : "r"(addr))

// mma.sync m16n8k16 fp16 -> fp32
__device__ __forceinline__ void mma_f16(float* d, const uint32_t* a, const uint32_t* b) {
    asm volatile(
        "mma.sync.aligned.m16n8k16.row.col.f32.f16.f16.f32 "
        "{%0,%1,%2,%3},{%4,%5,%6,%7},{%8,%9},{%0,%1,%2,%3};"
        : "+f"(d[0]), "+f"(d[1]), "+f"(d[2]), "+f"(d[3])
        : "r"(a[0]), "r"(a[1]), "r"(a[2]), "r"(a[3]), "r"(b[0]), "r"(b[1]));
}

// ---------------- fp16 mma GEMM NT: C[M,N] = A[M,K] @ B[N,K]^T (+resid) ------
// BM=BN=128, BK=64 halves, 256 threads (8 warps 2x4), warp tile 64x32, 3-stage,
// ldmatrix fragment loads.
#define BM 128
#define BN 128
#define BK 64
#define SAW 36                                // smem row stride in 32-bit words
#define TILE_B (BM * SAW * 4)                 // 18432 bytes per tile
#define STAGE_B (2 * TILE_B)                  // A+B per stage
#define GEMM_SMEM (3 * STAGE_B)               // 110592

__device__ __forceinline__ void load_tile(const __half* __restrict__ Ag,
                                          const __half* __restrict__ Bg, int K,
                                          uint32_t base, int stage, int tid, int k0) {
    uint32_t ab = base + stage * STAGE_B;
    uint32_t bb = ab + TILE_B;
    #pragma unroll
    for (int i = 0; i < 4; i++) {
        int idx = tid + i * 256;
        int r = idx >> 3, c = idx & 7;        // 128 rows x 8 chunks(16B = 8 halves)
        uint32_t off = r * (SAW * 4) + c * 16;
        CP_ASYNC16(ab + off, Ag + (size_t)r * K + k0 + c * 8);
        CP_ASYNC16(bb + off, Bg + (size_t)r * K + k0 + c * 8);
    }
}

template <bool HALF_OUT>
__global__ __launch_bounds__(256, 2)
void gemm_f16(const __half* __restrict__ A, const __half* __restrict__ B,
              const float* __restrict__ resid, void* __restrict__ Cv,
              int M, int N, int K) {
    extern __shared__ char smem[];
    uint32_t s0 = smem_to_u32(smem);
    int tid = threadIdx.x;
    int warp = tid >> 5, lane = tid & 31;
    int wm = warp >> 2, wn = warp & 3;
    int g = lane >> 2, tg = lane & 3;
    int bn = blockIdx.x, bm = blockIdx.y;

    const __half* Ag = A + (size_t)bm * BM * K;
    const __half* Bg = B + (size_t)bn * BN * K;
    int T = K / BK;

    // ldmatrix per-lane byte offsets (within a stage's A or B tile)
    uint32_t lr = lane & 7, quad = (uint32_t)lane >> 3;
    uint32_t woff = (quad >> 1) * 4;                     // word offset within kstep
    uint32_t aoffb[4], boffb[2];
    #pragma unroll
    for (int mi = 0; mi < 4; mi++)
        aoffb[mi] = ((wm * 64 + mi * 16 + (quad & 1) * 8 + lr) * SAW + woff) * 4;
    #pragma unroll
    for (int p = 0; p < 2; p++)
        boffb[p] = ((wn * 32 + p * 16 + (quad & 1) * 8 + lr) * SAW + woff) * 4;

    float acc[4][4][4];
    #pragma unroll
    for (int mi = 0; mi < 4; mi++)
        #pragma unroll
        for (int ni = 0; ni < 4; ni++)
            #pragma unroll
            for (int r = 0; r < 4; r++) acc[mi][ni][r] = 0.f;

    load_tile(Ag, Bg, K, s0, 0, tid, 0);
    CP_COMMIT();
    load_tile(Ag, Bg, K, s0, 1, tid, BK);
    CP_COMMIT();

    for (int t = 0; t < T; t++) {
        CP_WAIT1();                            // stage t complete (2 groups in flight)
        __syncthreads();
        int tn = t + 2;
        if (tn < T) load_tile(Ag, Bg, K, s0, tn % 3, tid, tn * BK);
        CP_COMMIT();                           // invariant: 2 pending groups
        uint32_t abase = s0 + (t % 3) * STAGE_B;
        uint32_t bbase = abase + TILE_B;
        #pragma unroll
        for (int ks = 0; ks < 4; ks++) {
            uint32_t kb = ks * 32;             // 8 words per kstep
            uint32_t a[4][4], b[4][2];
            #pragma unroll
            for (int mi = 0; mi < 4; mi++)
                LDSM_X4(a[mi][0], a[mi][1], a[mi][2], a[mi][3], abase + aoffb[mi] + kb);
            #pragma unroll
            for (int p = 0; p < 2; p++)
                LDSM_X4(b[2*p][0], b[2*p+1][0], b[2*p][1], b[2*p+1][1], bbase + boffb[p] + kb);
            #pragma unroll
            for (int mi = 0; mi < 4; mi++)
                #pragma unroll
                for (int ni = 0; ni < 4; ni++)
                    mma_f16(acc[mi][ni], a[mi], b[ni]);
        }
    }

    #pragma unroll
    for (int mi = 0; mi < 4; mi++) {
        int r0 = bm * BM + wm * 64 + mi * 16 + g;
        #pragma unroll
        for (int ni = 0; ni < 4; ni++) {
            int c = bn * BN + wn * 32 + ni * 8 + tg * 2;
            size_t o0 = (size_t)r0 * N + c;
            size_t o1 = (size_t)(r0 + 8) * N + c;
            if (HALF_OUT) {
                __half* C = (__half*)Cv;
                __half2 h0 = __floats2half2_rn(acc[mi][ni][0], acc[mi][ni][1]);
                __half2 h1 = __floats2half2_rn(acc[mi][ni][2], acc[mi][ni][3]);
                *(__half2*)(C + o0) = h0;
                *(__half2*)(C + o1) = h1;
            } else {
                float* C = (float*)Cv;
                float2 v0 = make_float2(acc[mi][ni][0], acc[mi][ni][1]);
                float2 v1 = make_float2(acc[mi][ni][2], acc[mi][ni][3]);
                if (resid) {
                    float2 q0 = *(const float2*)(resid + o0);
                    float2 q1 = *(const float2*)(resid + o1);
                    v0.x += q0.x; v0.y += q0.y;
                    v1.x += q1.x; v1.y += q1.y;
                }
                *(float2*)(C + o0) = v0;
                *(float2*)(C + o1) = v1;
            }
        }
    }
}

// ---------------- weights fp32 -> fp16 ----------------
__global__ void wconv_kernel(const float* __restrict__ w, __half* __restrict__ o) {
    int i = blockIdx.x * 256 + threadIdx.x;          // over WTOTAL/4
    float4 v = ((const float4*)w)[i];
    __half2 h0 = __floats2half2_rn(v.x, v.y);
    __half2 h1 = __floats2half2_rn(v.z, v.w);
    ((uint2*)o)[i] = make_uint2(*(uint32_t*)&h0, *(uint32_t*)&h1);
}

// ---------------- RMSNorm (fp32 in, half out) ----------------
__global__ void rmsnorm_kernel(const float* __restrict__ x, const float* __restrict__ w,
                               __half* __restrict__ y) {
    int s = blockIdx.x;
    int tid = threadIdx.x;          // 256
    const float4* xr = (const float4*)(x + (size_t)s * HDIM);
    const float4* wr = (const float4*)w;
    float4 v0 = xr[tid];
    float4 v1 = xr[tid + 256];
    float ss = v0.x*v0.x + v0.y*v0.y + v0.z*v0.z + v0.w*v0.w
             + v1.x*v1.x + v1.y*v1.y + v1.z*v1.z + v1.w*v1.w;
    __shared__ float red[8];
    #pragma unroll
    for (int o = 16; o; o >>= 1) ss += __shfl_xor_sync(0xffffffffu, ss, o);
    if ((tid & 31) == 0) red[tid >> 5] = ss;
    __syncthreads();
    if (tid < 8) {
        float t = red[tid];
        #pragma unroll
        for (int o = 4; o; o >>= 1) t += __shfl_xor_sync(0xffu, t, o);
        if (tid == 0) red[0] = t;
    }
    __syncthreads();
    float inv = rsqrtf(red[0] * (1.0f / HDIM) + 1e-6f);
    float4 w0 = wr[tid], w1 = wr[tid + 256];
    uint2* yr = (uint2*)(y + (size_t)s * HDIM);
    __half2 a0 = __floats2half2_rn(v0.x*w0.x*inv, v0.y*w0.y*inv);
    __half2 a1 = __floats2half2_rn(v0.z*w0.z*inv, v0.w*w0.w*inv);
    __half2 b0 = __floats2half2_rn(v1.x*w1.x*inv, v1.y*w1.y*inv);
    __half2 b1 = __floats2half2_rn(v1.z*w1.z*inv, v1.w*w1.w*inv);
    yr[tid]       = make_uint2(*(uint32_t*)&a0, *(uint32_t*)&a1);
    yr[tid + 256] = make_uint2(*(uint32_t*)&b0, *(uint32_t*)&b1);
}

// ---------------- RoPE in place on half qkv (q+k heads only) ----------------
__global__ void rope_kernel(__half* __restrict__ qkvh, const float* __restrict__ cs,
                            const float* __restrict__ sn) {
    int lane = threadIdx.x & 31;
    int w = threadIdx.x >> 5;
    int hh = blockIdx.y * 8 + w;             // 0..23 (16 q + 8 k heads)
    int s = blockIdx.x;
    int base = (hh < NH) ? hh * HD : HDIM + (hh - NH) * HD;
    __half* p = qkvh + (size_t)s * QKV_N + base;
    int d = lane * 2;
    float2 c1 = *(const float2*)(cs + s * HD + d);
    float2 s1 = *(const float2*)(sn + s * HD + d);
    float2 c2 = *(const float2*)(cs + s * HD + d + 64);
    float2 s2 = *(const float2*)(sn + s * HD + d + 64);
    float2 x1 = __half22float2(*(__half2*)(p + d));
    float2 x2 = __half22float2(*(__half2*)(p + d + 64));
    *(__half2*)(p + d)      = __floats2half2_rn(x1.x * c1.x - x2.x * s1.x,
                                                x1.y * c1.y - x2.y * s1.y);
    *(__half2*)(p + d + 64) = __floats2half2_rn(x2.x * c2.x + x1.x * s2.x,
                                                x2.y * c2.y + x1.y * s2.y);
}

// ---------------- Flash attention (causal, GQA rep=2), fp16 mma + ldmatrix ---
#define QSTRH 136
#define QSTRW 68
#define VSTRH 72
#define VSTRW 36
#define ATT_Q_H (128 * QSTRH)
#define ATT_K_H (64 * QSTRH)
#define ATT_V_H (128 * VSTRH)
#define ATT_SMEM ((ATT_Q_H + ATT_K_H + ATT_V_H) * 2)   // 70656 bytes

__global__ __launch_bounds__(256)
void attn_f16(const __half* __restrict__ qkvh, __half* __restrict__ outh) {
    extern __shared__ __half ash[];
    __half* Qs = ash;
    __half* Ks = Qs + ATT_Q_H;
    __half* Vt = Ks + ATT_K_H;
    uint32_t qbase = smem_to_u32(Qs);
    uint32_t kbase = smem_to_u32(Ks);
    uint32_t vbase = smem_to_u32(Vt);

    int bid = blockIdx.x;
    int h = bid & 15;
    int p = bid >> 4;
    int qt = (p < 8) ? (15 - p) : (p - 8);   // heavy tiles first
    int tid = threadIdx.x;
    int warp = tid >> 5, lane = tid & 31;
    int g = lane >> 2, tg = lane & 3;
    int kvh = h >> 1;
    const float scale = 0.08838834764831845f;   // 1/sqrt(128)

    // ldmatrix per-lane offsets
    uint32_t lr = lane & 7, quad = (uint32_t)lane >> 3;
    uint32_t woff = (quad >> 1) * 4;
    uint32_t qoffb = ((warp * 16 + (quad & 1) * 8 + lr) * QSTRW + woff) * 4;
    uint32_t koffb[4], voffb[8];
    #pragma unroll
    for (int pp = 0; pp < 4; pp++)
        koffb[pp] = ((pp * 16 + (quad & 1) * 8 + lr) * QSTRW + woff) * 4;
    #pragma unroll
    for (int pp = 0; pp < 8; pp++)
        voffb[pp] = ((pp * 16 + (quad & 1) * 8 + lr) * VSTRW + woff) * 4;

    // load Q tile: 128 rows x 16 chunks(8 halves)
    #pragma unroll
    for (int i = 0; i < 8; i++) {
        int idx = tid + i * 256;
        int r = idx >> 4, c = idx & 15;
        *(uint4*)(Qs + r * QSTRH + c * 8) =
            *(const uint4*)(qkvh + (size_t)(qt * 128 + r) * QKV_N + h * HD + c * 8);
    }

    float o[16][4];
    #pragma unroll
    for (int nt = 0; nt < 16; nt++)
        #pragma unroll
        for (int r = 0; r < 4; r++) o[nt][r] = 0.f;
    float m0 = -INFINITY, m1 = -INFINITY, l0 = 0.f, l1 = 0.f;

    int row0 = qt * 128 + warp * 16 + g;
    int row1 = row0 + 8;

    int nkt = 2 * qt + 2;
    for (int kt = 0; kt < nkt; kt++) {
        __syncthreads();
        // load K tile (64 x 128 halves)
        #pragma unroll
        for (int i = 0; i < 4; i++) {
            int idx = tid + i * 256;
            int r = idx >> 4, c = idx & 15;
            *(uint4*)(Ks + r * QSTRH + c * 8) =
                *(const uint4*)(qkvh + (size_t)(kt * 64 + r) * QKV_N + HDIM + kvh * HD + c * 8);
        }
        // load V transposed: Vt[n][k]
        {
            int n = tid & 127;
            int kw0 = (tid >> 7) * 16;
            const __half* vsrc = qkvh + (size_t)(kt * 64) * QKV_N + HDIM + NKV * HD + kvh * HD + n;
            #pragma unroll
            for (int wv = 0; wv < 16; wv++) {
                int k = (kw0 + wv) * 2;
                __half v0 = vsrc[(size_t)k * QKV_N];
                __half v1 = vsrc[(size_t)(k + 1) * QKV_N];
                *(__half2*)(Vt + n * VSTRH + k) = __halves2half2(v0, v1);
            }
        }
        __syncthreads();

        // S = Q @ K^T : warp computes 16x64
        float s[8][4];
        #pragma unroll
        for (int nt = 0; nt < 8; nt++)
            #pragma unroll
            for (int r = 0; r < 4; r++) s[nt][r] = 0.f;
        #pragma unroll
        for (int ks = 0; ks < 8; ks++) {
            uint32_t kb = ks * 32;
            uint32_t a[4], b[4][2];
            LDSM_X4(a[0], a[1], a[2], a[3], qbase + qoffb + kb);
            #pragma unroll
            for (int pp = 0; pp < 4; pp++) {
                uint32_t b0, b1, b2, b3;
                LDSM_X4(b0, b1, b2, b3, kbase + koffb[pp] + kb);
                b[0][0] = b0; b[1][0] = b1; b[0][1] = b2; b[1][1] = b3;
                mma_f16(s[2*pp],     a, b[0]);
                mma_f16(s[2*pp + 1], a, b[1]);
            }
        }

        // softmax (fp32), causal mask on diagonal tiles
        bool diag = (kt >= 2 * qt);
        float tm0 = -INFINITY, tm1 = -INFINITY;
        #pragma unroll
        for (int nt = 0; nt < 8; nt++) {
            #pragma unroll
            for (int r = 0; r < 4; r++) s[nt][r] *= scale;
            if (diag) {
                int c0 = kt * 64 + nt * 8 + 2 * tg;
                if (c0 > row0)     s[nt][0] = -INFINITY;
                if (c0 + 1 > row0) s[nt][1] = -INFINITY;
                if (c0 > row1)     s[nt][2] = -INFINITY;
                if (c0 + 1 > row1) s[nt][3] = -INFINITY;
            }
            tm0 = fmaxf(tm0, fmaxf(s[nt][0], s[nt][1]));
            tm1 = fmaxf(tm1, fmaxf(s[nt][2], s[nt][3]));
        }
        tm0 = fmaxf(tm0, __shfl_xor_sync(0xffffffffu, tm0, 1));
        tm0 = fmaxf(tm0, __shfl_xor_sync(0xffffffffu, tm0, 2));
        tm1 = fmaxf(tm1, __shfl_xor_sync(0xffffffffu, tm1, 1));
        tm1 = fmaxf(tm1, __shfl_xor_sync(0xffffffffu, tm1, 2));
        float mn0 = fmaxf(m0, tm0), mn1 = fmaxf(m1, tm1);
        float corr0 = __expf(m0 - mn0), corr1 = __expf(m1 - mn1);

        uint32_t ph0[8], ph1[8];
        float ls0 = 0.f, ls1 = 0.f;
        #pragma unroll
        for (int nt = 0; nt < 8; nt++) {
            float p00 = __expf(s[nt][0] - mn0);
            float p01 = __expf(s[nt][1] - mn0);
            float p10 = __expf(s[nt][2] - mn1);
            float p11 = __expf(s[nt][3] - mn1);
            ls0 += p00 + p01; ls1 += p10 + p11;
            __half2 h0 = __floats2half2_rn(p00, p01);
            __half2 h1 = __floats2half2_rn(p10, p11);
            ph0[nt] = *(uint32_t*)&h0;
            ph1[nt] = *(uint32_t*)&h1;
        }
        ls0 += __shfl_xor_sync(0xffffffffu, ls0, 1);
        ls0 += __shfl_xor_sync(0xffffffffu, ls0, 2);
        ls1 += __shfl_xor_sync(0xffffffffu, ls1, 1);
        ls1 += __shfl_xor_sync(0xffffffffu, ls1, 2);
        l0 = l0 * corr0 + ls0;
        l1 = l1 * corr1 + ls1;
        m0 = mn0; m1 = mn1;
        #pragma unroll
        for (int nt = 0; nt < 16; nt++) {
            o[nt][0] *= corr0; o[nt][1] *= corr0;
            o[nt][2] *= corr1; o[nt][3] *= corr1;
        }

        // O += P @ V : 4 ksteps of 16; A frags from registers
        #pragma unroll
        for (int ks = 0; ks < 4; ks++) {
            uint32_t a[4];
            a[0] = ph0[2 * ks];
            a[1] = ph1[2 * ks];
            a[2] = ph0[2 * ks + 1];
            a[3] = ph1[2 * ks + 1];
            uint32_t kb = ks * 32;
            #pragma unroll
            for (int pp = 0; pp < 8; pp++) {
                uint32_t b0, b1, b2, b3;
                LDSM_X4(b0, b1, b2, b3, vbase + voffb[pp] + kb);
                uint32_t bb0[2] = {b0, b2}, bb1[2] = {b1, b3};
                mma_f16(o[2*pp],     a, bb0);
                mma_f16(o[2*pp + 1], a, bb1);
            }
        }
    }

    float inv0 = 1.f / l0, inv1 = 1.f / l1;
    #pragma unroll
    for (int nt = 0; nt < 16; nt++) {
        int col = h * HD + nt * 8 + 2 * tg;
        __half2 w0 = __floats2half2_rn(o[nt][0] * inv0, o[nt][1] * inv0);
        __half2 w1 = __floats2half2_rn(o[nt][2] * inv1, o[nt][3] * inv1);
        *(__half2*)(outh + (size_t)row0 * HDIM + col) = w0;
        *(__half2*)(outh + (size_t)row1 * HDIM + col) = w1;
    }
}

// ---------------- SiLU(gate) * up (half in, half out) ----------------
__global__ void silu_mul_kernel(const __half* __restrict__ gu, __half* __restrict__ o) {
    int idx = blockIdx.x * 256 + threadIdx.x;   // over SLEN*IDIM/8
    int s = idx >> 10;
    int c = idx & 1023;
    uint4 uu = *((const uint4*)(gu + (size_t)s * 2 * IDIM) + c);
    uint4 gg = *((const uint4*)(gu + (size_t)s * 2 * IDIM + IDIM) + c);
    const __half2* up = (const __half2*)&uu;
    const __half2* gt = (const __half2*)&gg;
    uint4 out;
    __half2* oh = (__half2*)&out;
    #pragma unroll
    for (int i = 0; i < 4; i++) {
        float2 u = __half22float2(up[i]);
        float2 g = __half22float2(gt[i]);
        float r0 = u.x * (g.x / (1.f + __expf(-g.x)));
        float r1 = u.y * (g.y / (1.f + __expf(-g.y)));
        oh[i] = __floats2half2_rn(r0, r1);
    }
    *((uint4*)(o + (size_t)s * IDIM) + c) = out;
}

// ---------------- launch ----------------
extern "C" void kernel_launch(void* const* d_in, const int* in_sizes, int n_in,
                              void* d_out, int out_size) {
    const float* hidden = (const float*)d_in[0];
    const float* wflat  = (const float*)d_in[1];
    const float* ln1    = (const float*)d_in[2];
    const float* ln2    = (const float*)d_in[3];
    const float* cosb   = (const float*)d_in[4];
    const float* sinb   = (const float*)d_in[5];
    float* out = (float*)d_out;

    __half *wh, *xh, *qkvh, *attnh, *guh, *h1h;
    float *hid;
    cudaGetSymbolAddress((void**)&wh,    g_wh);
    cudaGetSymbolAddress((void**)&xh,    g_xh);
    cudaGetSymbolAddress((void**)&qkvh,  g_qkvh);
    cudaGetSymbolAddress((void**)&attnh, g_attnh);
    cudaGetSymbolAddress((void**)&hid,   g_hid);
    cudaGetSymbolAddress((void**)&guh,   g_guh);
    cudaGetSymbolAddress((void**)&h1h,   g_h1h);

    cudaFuncSetAttribute(gemm_f16<false>, cudaFuncAttributeMaxDynamicSharedMemorySize, GEMM_SMEM);
    cudaFuncSetAttribute(gemm_f16<true>,  cudaFuncAttributeMaxDynamicSharedMemorySize, GEMM_SMEM);
    cudaFuncSetAttribute(attn_f16, cudaFuncAttributeMaxDynamicSharedMemorySize, ATT_SMEM);

    // 0) weights fp32 -> fp16
    wconv_kernel<<<WTOTAL / 4 / 256, 256>>>(wflat, wh);
    // 1) input rmsnorm -> half
    rmsnorm_kernel<<<SLEN, 256>>>(hidden, ln1, xh);
    // 2) fused QKV projection -> half
    gemm_f16<true><<<dim3(QKV_N / BN, SLEN / BM), 256, GEMM_SMEM>>>(xh, wh, nullptr, qkvh,
                                                                    SLEN, QKV_N, HDIM);
    // 3) RoPE in place on half (q+k heads)
    rope_kernel<<<dim3(SLEN, 3), 256>>>(qkvh, cosb, sinb);
    // 4) causal attention (fp16 mma, fp32 softmax)
    attn_f16<<<256, 256, ATT_SMEM>>>(qkvh, attnh);
    // 5) o-projection + residual (fp32 out)
    gemm_f16<false><<<dim3(HDIM / BN, SLEN / BM), 256, GEMM_SMEM>>>(attnh, wh + 8388608,
                                                                    hidden, hid,
                                                                    SLEN, HDIM, HDIM);
    // 6) post-attention rmsnorm -> half
    rmsnorm_kernel<<<SLEN, 256>>>(hid, ln2, xh);
    // 7) fused up|gate projection -> half
    gemm_f16<true><<<dim3(2 * IDIM / BN, SLEN / BM), 256, GEMM_SMEM>>>(xh, wh + 12582912,
                                                                       nullptr, guh,
                                                                       SLEN, 2 * IDIM, HDIM);
    // 8) silu(gate)*up -> half
    silu_mul_kernel<<<(SLEN * IDIM / 8) / 256, 256>>>(guh, h1h);
    // 9) down projection + residual -> output (fp32)
    gemm_f16<false><<<dim3(HDIM / BN, SLEN / BM), 256, GEMM_SMEM>>>(h1h, wh + 46137344,
                                                                    hid, out,
                                                                    SLEN, HDIM, IDIM);
}

// round 8
// speedup vs baseline: 8.7736x; 1.0130x over previous
#include <cuda_runtime.h>
#include <cuda_fp16.h>
#include <math.h>
#include <stdint.h>

#define HDIM 2048
#define SLEN 2048
#define NH 16
#define NKV 8
#define HD 128
#define IDIM 8192
#define QKV_N 4096
#define WTOTAL 62914560

// weight region offsets (floats)
#define W_O    8388608
#define W_UP   12582912
#define W_GATE 29360128
#define W_DOWN 46137344

// ---------------- scratch (device globals; no allocation) ----------------
__device__ __half g_wh   [(size_t)WTOTAL];           // fp16 weights (mlp interleaved)
__device__ __half g_xh   [(size_t)SLEN * HDIM];      // normed activations (half)
__device__ __half g_qkvh [(size_t)SLEN * QKV_N];     // qkv half (rope in place)
__device__ __half g_attnh[(size_t)SLEN * HDIM];      // attention out (half)
__device__ float  g_hid  [(size_t)SLEN * HDIM];      // residual stream fp32
__device__ __half g_h1h  [(size_t)SLEN * IDIM];      // silu(gate)*up (half)

// ---------------- helpers ----------------
__device__ __forceinline__ uint32_t smem_to_u32(const void* p) {
    uint32_t a;
    asm("{ .reg .u64 t; cvta.to.shared.u64 t, %1; cvt.u32.u64 %0, t; }" : "=r"(a) : "l"(p));
    return a;
}
#define CP_ASYNC16(s, g) asm volatile("cp.async.cg.shared.global [%0], [%1], 16;" :: "r"(s), "l"(g))
#define CP_COMMIT() asm volatile("cp.async.commit_group;" ::: "memory")
#define CP_WAIT0() asm volatile("cp.async.wait_group 0;" ::: "memory")
#define CP_WAIT1() asm volatile("cp.async.wait_group 1;" ::: "memory")

#define LDSM_X4(r0, r1, r2, r3, addr) \
    asm volatile("ldmatrix.sync.aligned.m8n8.x4.shared.b16 {%0,%1,%2,%3}, [%4];" \
        : "=r"(r0), "=r"(r1), "=r"(r2), "=r"(r3) : "r"(addr))
#define LDSM_X4_T(r0, r1, r2, r3, addr) \
    asm volatile("ldmatrix.sync.aligned.m8n8.x4.trans.shared.b16 {%0,%1,%2,%3}, [%4];" \
        : "=r"(r0), "=r"(r1), "=r"(r2), "=r"(r3) : "r"(addr))

// mma.sync m16n8k16 fp16 -> fp32
__device__ __forceinline__ void mma_f16(float* d, const uint32_t* a, const uint32_t* b) {
    asm volatile(
        "mma.sync.aligned.m16n8k16.row.col.f32.f16.f16.f32 "
        "{%0,%1,%2,%3},{%4,%5,%6,%7},{%8,%9},{%0,%1,%2,%3};"
        : "+f"(d[0]), "+f"(d[1]), "+f"(d[2]), "+f"(d[3])
        : "r"(a[0]), "r"(a[1]), "r"(a[2]), "r"(a[3]), "r"(b[0]), "r"(b[1]));
}

// ---------------- fp16 mma GEMM NT: C[M,N] = A[M,K] @ B[N,K]^T ---------------
// MODE 0: fp32 out (+resid). MODE 1: half out. MODE 2: fused silu, half out N/2.
#define BM 128
#define BN 128
#define BK 64
#define SAW 36                                // smem row stride in 32-bit words
#define TILE_B (BM * SAW * 4)                 // 18432 bytes per tile
#define STAGE_B (2 * TILE_B)
#define GEMM_SMEM (3 * STAGE_B)               // 110592

__device__ __forceinline__ void load_tile(const __half* __restrict__ Ag,
                                          const __half* __restrict__ Bg, int K,
                                          uint32_t base, int stage, int tid, int k0) {
    uint32_t ab = base + stage * STAGE_B;
    uint32_t bb = ab + TILE_B;
    #pragma unroll
    for (int i = 0; i < 4; i++) {
        int idx = tid + i * 256;
        int r = idx >> 3, c = idx & 7;
        uint32_t off = r * (SAW * 4) + c * 16;
        CP_ASYNC16(ab + off, Ag + (size_t)r * K + k0 + c * 8);
        CP_ASYNC16(bb + off, Bg + (size_t)r * K + k0 + c * 8);
    }
}

template <int MODE>
__global__ __launch_bounds__(256, 2)
void gemm_f16(const __half* __restrict__ A, const __half* __restrict__ B,
              const float* __restrict__ resid, void* __restrict__ Cv,
              int M, int N, int K) {
    extern __shared__ char smem[];
    uint32_t s0 = smem_to_u32(smem);
    int tid = threadIdx.x;
    int warp = tid >> 5, lane = tid & 31;
    int wm = warp >> 2, wn = warp & 3;
    int g = lane >> 2, tg = lane & 3;
    int bn = blockIdx.x, bm = blockIdx.y;

    const __half* Ag = A + (size_t)bm * BM * K;
    const __half* Bg = B + (size_t)bn * BN * K;
    int T = K / BK;

    uint32_t lr = lane & 7, quad = (uint32_t)lane >> 3;
    uint32_t woff = (quad >> 1) * 4;
    uint32_t aoffb[4], boffb[2];
    #pragma unroll
    for (int mi = 0; mi < 4; mi++)
        aoffb[mi] = ((wm * 64 + mi * 16 + (quad & 1) * 8 + lr) * SAW + woff) * 4;
    #pragma unroll
    for (int p = 0; p < 2; p++)
        boffb[p] = ((wn * 32 + p * 16 + (quad & 1) * 8 + lr) * SAW + woff) * 4;

    float acc[4][4][4];
    #pragma unroll
    for (int mi = 0; mi < 4; mi++)
        #pragma unroll
        for (int ni = 0; ni < 4; ni++)
            #pragma unroll
            for (int r = 0; r < 4; r++) acc[mi][ni][r] = 0.f;

    load_tile(Ag, Bg, K, s0, 0, tid, 0);
    CP_COMMIT();
    load_tile(Ag, Bg, K, s0, 1, tid, BK);
    CP_COMMIT();

    for (int t = 0; t < T; t++) {
        CP_WAIT1();
        __syncthreads();
        int tn = t + 2;
        if (tn < T) load_tile(Ag, Bg, K, s0, tn % 3, tid, tn * BK);
        CP_COMMIT();
        uint32_t abase = s0 + (t % 3) * STAGE_B;
        uint32_t bbase = abase + TILE_B;
        #pragma unroll
        for (int ks = 0; ks < 4; ks++) {
            uint32_t kb = ks * 32;
            uint32_t a[4][4], b[4][2];
            #pragma unroll
            for (int mi = 0; mi < 4; mi++)
                LDSM_X4(a[mi][0], a[mi][1], a[mi][2], a[mi][3], abase + aoffb[mi] + kb);
            #pragma unroll
            for (int p = 0; p < 2; p++)
                LDSM_X4(b[2*p][0], b[2*p+1][0], b[2*p][1], b[2*p+1][1], bbase + boffb[p] + kb);
            #pragma unroll
            for (int mi = 0; mi < 4; mi++)
                #pragma unroll
                for (int ni = 0; ni < 4; ni++)
                    mma_f16(acc[mi][ni], a[mi], b[ni]);
        }
    }

    #pragma unroll
    for (int mi = 0; mi < 4; mi++) {
        int r0 = bm * BM + wm * 64 + mi * 16 + g;
        #pragma unroll
        for (int ni = 0; ni < 4; ni++) {
            int c = bn * BN + wn * 32 + ni * 8 + tg * 2;
            if (MODE == 2) {                    // fused silu: (up, gate) pair
                __half* C = (__half*)Cv;
                int NO = N >> 1;
                int j = c >> 1;
                float u0 = acc[mi][ni][0], g0 = acc[mi][ni][1];
                float u1 = acc[mi][ni][2], g1 = acc[mi][ni][3];
                float v0 = u0 * (g0 / (1.f + __expf(-g0)));
                float v1 = u1 * (g1 / (1.f + __expf(-g1)));
                C[(size_t)r0 * NO + j]       = __float2half_rn(v0);
                C[(size_t)(r0 + 8) * NO + j] = __float2half_rn(v1);
            } else if (MODE == 1) {
                __half* C = (__half*)Cv;
                size_t o0 = (size_t)r0 * N + c;
                size_t o1 = (size_t)(r0 + 8) * N + c;
                *(__half2*)(C + o0) = __floats2half2_rn(acc[mi][ni][0], acc[mi][ni][1]);
                *(__half2*)(C + o1) = __floats2half2_rn(acc[mi][ni][2], acc[mi][ni][3]);
            } else {
                float* C = (float*)Cv;
                size_t o0 = (size_t)r0 * N + c;
                size_t o1 = (size_t)(r0 + 8) * N + c;
                float2 v0 = make_float2(acc[mi][ni][0], acc[mi][ni][1]);
                float2 v1 = make_float2(acc[mi][ni][2], acc[mi][ni][3]);
                float2 q0 = *(const float2*)(resid + o0);
                float2 q1 = *(const float2*)(resid + o1);
                v0.x += q0.x; v0.y += q0.y;
                v1.x += q1.x; v1.y += q1.y;
                *(float2*)(C + o0) = v0;
                *(float2*)(C + o1) = v1;
            }
        }
    }
}

// ---------------- weights fp32 -> fp16 (mlp region row-interleaved) ----------
__global__ void wconv_kernel(const float* __restrict__ w, __half* __restrict__ o) {
    size_t i = (size_t)blockIdx.x * 256 + threadIdx.x;   // float4 index
    size_t f = i * 4;
    size_t src = f;
    if (f >= (size_t)W_UP && f < (size_t)W_DOWN) {
        size_t rel = f - W_UP;
        size_t r = rel >> 11, c = rel & 2047;
        src = ((r & 1) ? (size_t)W_GATE : (size_t)W_UP) + (r >> 1) * 2048 + c;
    }
    float4 v = *(const float4*)(w + src);
    __half2 h0 = __floats2half2_rn(v.x, v.y);
    __half2 h1 = __floats2half2_rn(v.z, v.w);
    ((uint2*)o)[i] = make_uint2(*(uint32_t*)&h0, *(uint32_t*)&h1);
}

// ---------------- RMSNorm (fp32 in, half out) ----------------
__global__ void rmsnorm_kernel(const float* __restrict__ x, const float* __restrict__ w,
                               __half* __restrict__ y) {
    int s = blockIdx.x;
    int tid = threadIdx.x;
    const float4* xr = (const float4*)(x + (size_t)s * HDIM);
    const float4* wr = (const float4*)w;
    float4 v0 = xr[tid];
    float4 v1 = xr[tid + 256];
    float ss = v0.x*v0.x + v0.y*v0.y + v0.z*v0.z + v0.w*v0.w
             + v1.x*v1.x + v1.y*v1.y + v1.z*v1.z + v1.w*v1.w;
    __shared__ float red[8];
    #pragma unroll
    for (int o = 16; o; o >>= 1) ss += __shfl_xor_sync(0xffffffffu, ss, o);
    if ((tid & 31) == 0) red[tid >> 5] = ss;
    __syncthreads();
    if (tid < 8) {
        float t = red[tid];
        #pragma unroll
        for (int o = 4; o; o >>= 1) t += __shfl_xor_sync(0xffu, t, o);
        if (tid == 0) red[0] = t;
    }
    __syncthreads();
    float inv = rsqrtf(red[0] * (1.0f / HDIM) + 1e-6f);
    float4 w0 = wr[tid], w1 = wr[tid + 256];
    uint2* yr = (uint2*)(y + (size_t)s * HDIM);
    __half2 a0 = __floats2half2_rn(v0.x*w0.x*inv, v0.y*w0.y*inv);
    __half2 a1 = __floats2half2_rn(v0.z*w0.z*inv, v0.w*w0.w*inv);
    __half2 b0 = __floats2half2_rn(v1.x*w1.x*inv, v1.y*w1.y*inv);
    __half2 b1 = __floats2half2_rn(v1.z*w1.z*inv, v1.w*w1.w*inv);
    yr[tid]       = make_uint2(*(uint32_t*)&a0, *(uint32_t*)&a1);
    yr[tid + 256] = make_uint2(*(uint32_t*)&b0, *(uint32_t*)&b1);
}

// ---------------- RoPE in place on half qkv (q+k heads) ----------------
__global__ void rope_kernel(__half* __restrict__ qkvh, const float* __restrict__ cs,
                            const float* __restrict__ sn) {
    int lane = threadIdx.x & 31;
    int w = threadIdx.x >> 5;
    int hh = blockIdx.y * 8 + w;
    int s = blockIdx.x;
    int base = (hh < NH) ? hh * HD : HDIM + (hh - NH) * HD;
    __half* p = qkvh + (size_t)s * QKV_N + base;
    int d = lane * 2;
    float2 c1 = *(const float2*)(cs + s * HD + d);
    float2 s1 = *(const float2*)(sn + s * HD + d);
    float2 c2 = *(const float2*)(cs + s * HD + d + 64);
    float2 s2 = *(const float2*)(sn + s * HD + d + 64);
    float2 x1 = __half22float2(*(__half2*)(p + d));
    float2 x2 = __half22float2(*(__half2*)(p + d + 64));
    *(__half2*)(p + d)      = __floats2half2_rn(x1.x * c1.x - x2.x * s1.x,
                                                x1.y * c1.y - x2.y * s1.y);
    *(__half2*)(p + d + 64) = __floats2half2_rn(x2.x * c2.x + x1.x * s2.x,
                                                x2.y * c2.y + x1.y * s2.y);
}

// ---------------- Flash attention: fp16 mma, cp.async double-buffered K/V,
//                  ldmatrix.trans for V (no transpose pass) ------------------
#define QSTRH 136
#define QSTRW 68
#define KVROWB (QSTRH * 2)                    // 272 bytes per 128-half row
#define KVTILE_B (64 * KVROWB)                // 17408 bytes per K or V tile
#define ATT_Q_B (128 * KVROWB)                // 34816
#define ATT_SMEM (ATT_Q_B + 4 * KVTILE_B)     // 104448 bytes

__global__ __launch_bounds__(256)
void attn_f16(const __half* __restrict__ qkvh, __half* __restrict__ outh) {
    extern __shared__ __half ash[];
    uint32_t qbase = smem_to_u32(ash);
    uint32_t kbase = qbase + ATT_Q_B;
    uint32_t vbase = kbase + 2 * KVTILE_B;

    int bid = blockIdx.x;
    int h = bid & 15;
    int p = bid >> 4;
    int qt = (p < 8) ? (15 - p) : (p - 8);   // heavy tiles first
    int tid = threadIdx.x;
    int warp = tid >> 5, lane = tid & 31;
    int g = lane >> 2, tg = lane & 3;
    int kvh = h >> 1;
    const float scale = 0.08838834764831845f;

    uint32_t lr = lane & 7, quad = (uint32_t)lane >> 3;
    uint32_t woff = (quad >> 1) * 4;
    uint32_t qoffb = ((warp * 16 + (quad & 1) * 8 + lr) * QSTRW + woff) * 4;
    uint32_t koffb[4];
    #pragma unroll
    for (int pp = 0; pp < 4; pp++)
        koffb[pp] = ((pp * 16 + (quad & 1) * 8 + lr) * QSTRW + woff) * 4;
    // V trans ldmatrix lane offset: row=(quad&1)*8+lr (k), col quad>>1 (8 halves)
    uint32_t voffb = ((quad & 1) * 8 + lr) * KVROWB + (quad >> 1) * 16;

    // load Q tile (scaled not needed; scale applied post-mma)
    #pragma unroll
    for (int i = 0; i < 8; i++) {
        int idx = tid + i * 256;
        int r = idx >> 4, c = idx & 15;
        *(uint4*)((char*)ash + r * KVROWB + c * 16) =
            *(const uint4*)(qkvh + (size_t)(qt * 128 + r) * QKV_N + h * HD + c * 8);
    }

    const __half* ksrc = qkvh + HDIM + kvh * HD;
    const __half* vsrc = qkvh + HDIM + NKV * HD + kvh * HD;
    int nkt = 2 * qt + 2;

    // prologue: async load tile 0
    {
        uint32_t kb = kbase, vb = vbase;
        #pragma unroll
        for (int i = 0; i < 4; i++) {
            int idx = tid + i * 256;
            int r = idx >> 4, c = idx & 15;
            uint32_t off = r * KVROWB + c * 16;
            CP_ASYNC16(kb + off, ksrc + (size_t)r * QKV_N + c * 8);
            CP_ASYNC16(vb + off, vsrc + (size_t)r * QKV_N + c * 8);
        }
        CP_COMMIT();
    }

    float o[16][4];
    #pragma unroll
    for (int nt = 0; nt < 16; nt++)
        #pragma unroll
        for (int r = 0; r < 4; r++) o[nt][r] = 0.f;
    float m0 = -INFINITY, m1 = -INFINITY, l0 = 0.f, l1 = 0.f;

    int row0 = qt * 128 + warp * 16 + g;
    int row1 = row0 + 8;

    for (int kt = 0; kt < nkt; kt++) {
        CP_WAIT0();
        __syncthreads();
        if (kt + 1 < nkt) {
            uint32_t kb = kbase + ((kt + 1) & 1) * KVTILE_B;
            uint32_t vb = vbase + ((kt + 1) & 1) * KVTILE_B;
            const __half* kr = ksrc + (size_t)(kt + 1) * 64 * QKV_N;
            const __half* vr = vsrc + (size_t)(kt + 1) * 64 * QKV_N;
            #pragma unroll
            for (int i = 0; i < 4; i++) {
                int idx = tid + i * 256;
                int r = idx >> 4, c = idx & 15;
                uint32_t off = r * KVROWB + c * 16;
                CP_ASYNC16(kb + off, kr + (size_t)r * QKV_N + c * 8);
                CP_ASYNC16(vb + off, vr + (size_t)r * QKV_N + c * 8);
            }
            CP_COMMIT();
        }
        uint32_t kcur = kbase + (kt & 1) * KVTILE_B;
        uint32_t vcur = vbase + (kt & 1) * KVTILE_B;

        // S = Q @ K^T : warp computes 16x64
        float s[8][4];
        #pragma unroll
        for (int nt = 0; nt < 8; nt++)
            #pragma unroll
            for (int r = 0; r < 4; r++) s[nt][r] = 0.f;
        #pragma unroll
        for (int ks = 0; ks < 8; ks++) {
            uint32_t kb = ks * 32;
            uint32_t a[4], b[4][2];
            LDSM_X4(a[0], a[1], a[2], a[3], qbase + qoffb + kb);
            #pragma unroll
            for (int pp = 0; pp < 4; pp++) {
                uint32_t b0, b1, b2, b3;
                LDSM_X4(b0, b1, b2, b3, kcur + koffb[pp] + kb);
                b[0][0] = b0; b[1][0] = b1; b[0][1] = b2; b[1][1] = b3;
                mma_f16(s[2*pp],     a, b[0]);
                mma_f16(s[2*pp + 1], a, b[1]);
            }
        }

        // softmax (fp32)
        bool diag = (kt >= 2 * qt);
        float tm0 = -INFINITY, tm1 = -INFINITY;
        #pragma unroll
        for (int nt = 0; nt < 8; nt++) {
            #pragma unroll
            for (int r = 0; r < 4; r++) s[nt][r] *= scale;
            if (diag) {
                int c0 = kt * 64 + nt * 8 + 2 * tg;
                if (c0 > row0)     s[nt][0] = -INFINITY;
                if (c0 + 1 > row0) s[nt][1] = -INFINITY;
                if (c0 > row1)     s[nt][2] = -INFINITY;
                if (c0 + 1 > row1) s[nt][3] = -INFINITY;
            }
            tm0 = fmaxf(tm0, fmaxf(s[nt][0], s[nt][1]));
            tm1 = fmaxf(tm1, fmaxf(s[nt][2], s[nt][3]));
        }
        tm0 = fmaxf(tm0, __shfl_xor_sync(0xffffffffu, tm0, 1));
        tm0 = fmaxf(tm0, __shfl_xor_sync(0xffffffffu, tm0, 2));
        tm1 = fmaxf(tm1, __shfl_xor_sync(0xffffffffu, tm1, 1));
        tm1 = fmaxf(tm1, __shfl_xor_sync(0xffffffffu, tm1, 2));
        float mn0 = fmaxf(m0, tm0), mn1 = fmaxf(m1, tm1);
        float corr0 = __expf(m0 - mn0), corr1 = __expf(m1 - mn1);

        uint32_t ph0[8], ph1[8];
        float ls0 = 0.f, ls1 = 0.f;
        #pragma unroll
        for (int nt = 0; nt < 8; nt++) {
            float p00 = __expf(s[nt][0] - mn0);
            float p01 = __expf(s[nt][1] - mn0);
            float p10 = __expf(s[nt][2] - mn1);
            float p11 = __expf(s[nt][3] - mn1);
            ls0 += p00 + p01; ls1 += p10 + p11;
            __half2 h0 = __floats2half2_rn(p00, p01);
            __half2 h1 = __floats2half2_rn(p10, p11);
            ph0[nt] = *(uint32_t*)&h0;
            ph1[nt] = *(uint32_t*)&h1;
        }
        ls0 += __shfl_xor_sync(0xffffffffu, ls0, 1);
        ls0 += __shfl_xor_sync(0xffffffffu, ls0, 2);
        ls1 += __shfl_xor_sync(0xffffffffu, ls1, 1);
        ls1 += __shfl_xor_sync(0xffffffffu, ls1, 2);
        l0 = l0 * corr0 + ls0;
        l1 = l1 * corr1 + ls1;
        m0 = mn0; m1 = mn1;
        #pragma unroll
        for (int nt = 0; nt < 16; nt++) {
            o[nt][0] *= corr0; o[nt][1] *= corr0;
            o[nt][2] *= corr1; o[nt][3] *= corr1;
        }

        // O += P @ V : V natural [k][d], trans ldmatrix B frags
        #pragma unroll
        for (int ks = 0; ks < 4; ks++) {
            uint32_t a[4];
            a[0] = ph0[2 * ks];
            a[1] = ph1[2 * ks];
            a[2] = ph0[2 * ks + 1];
            a[3] = ph1[2 * ks + 1];
            uint32_t krow = ks * 16 * KVROWB;
            #pragma unroll
            for (int pp = 0; pp < 8; pp++) {
                uint32_t b0, b1, b2, b3;
                LDSM_X4_T(b0, b1, b2, b3, vcur + voffb + krow + pp * 32);
                uint32_t bb0[2] = {b0, b1}, bb1[2] = {b2, b3};
                mma_f16(o[2*pp],     a, bb0);
                mma_f16(o[2*pp + 1], a, bb1);
            }
        }
        __syncthreads();
    }

    float inv0 = 1.f / l0, inv1 = 1.f / l1;
    #pragma unroll
    for (int nt = 0; nt < 16; nt++) {
        int col = h * HD + nt * 8 + 2 * tg;
        __half2 w0 = __floats2half2_rn(o[nt][0] * inv0, o[nt][1] * inv0);
        __half2 w1 = __floats2half2_rn(o[nt][2] * inv1, o[nt][3] * inv1);
        *(__half2*)(outh + (size_t)row0 * HDIM + col) = w0;
        *(__half2*)(outh + (size_t)row1 * HDIM + col) = w1;
    }
}

// ---------------- launch ----------------
extern "C" void kernel_launch(void* const* d_in, const int* in_sizes, int n_in,
                              void* d_out, int out_size) {
    const float* hidden = (const float*)d_in[0];
    const float* wflat  = (const float*)d_in[1];
    const float* ln1    = (const float*)d_in[2];
    const float* ln2    = (const float*)d_in[3];
    const float* cosb   = (const float*)d_in[4];
    const float* sinb   = (const float*)d_in[5];
    float* out = (float*)d_out;

    __half *wh, *xh, *qkvh, *attnh, *h1h;
    float *hid;
    cudaGetSymbolAddress((void**)&wh,    g_wh);
    cudaGetSymbolAddress((void**)&xh,    g_xh);
    cudaGetSymbolAddress((void**)&qkvh,  g_qkvh);
    cudaGetSymbolAddress((void**)&attnh, g_attnh);
    cudaGetSymbolAddress((void**)&hid,   g_hid);
    cudaGetSymbolAddress((void**)&h1h,   g_h1h);

    cudaFuncSetAttribute(gemm_f16<0>, cudaFuncAttributeMaxDynamicSharedMemorySize, GEMM_SMEM);
    cudaFuncSetAttribute(gemm_f16<1>, cudaFuncAttributeMaxDynamicSharedMemorySize, GEMM_SMEM);
    cudaFuncSetAttribute(gemm_f16<2>, cudaFuncAttributeMaxDynamicSharedMemorySize, GEMM_SMEM);
    cudaFuncSetAttribute(attn_f16, cudaFuncAttributeMaxDynamicSharedMemorySize, ATT_SMEM);

    // 0) weights fp32 -> fp16 (mlp rows interleaved)
    wconv_kernel<<<WTOTAL / 4 / 256, 256>>>(wflat, wh);
    // 1) input rmsnorm -> half
    rmsnorm_kernel<<<SLEN, 256>>>(hidden, ln1, xh);
    // 2) fused QKV projection -> half
    gemm_f16<1><<<dim3(QKV_N / BN, SLEN / BM), 256, GEMM_SMEM>>>(xh, wh, nullptr, qkvh,
                                                                 SLEN, QKV_N, HDIM);
    // 3) RoPE in place on half (q+k heads)
    rope_kernel<<<dim3(SLEN, 3), 256>>>(qkvh, cosb, sinb);
    // 4) causal attention
    attn_f16<<<256, 256, ATT_SMEM>>>(qkvh, attnh);
    // 5) o-projection + residual (fp32 out)
    gemm_f16<0><<<dim3(HDIM / BN, SLEN / BM), 256, GEMM_SMEM>>>(attnh, wh + W_O,
                                                                hidden, hid,
                                                                SLEN, HDIM, HDIM);
    // 6) post-attention rmsnorm -> half
    rmsnorm_kernel<<<SLEN, 256>>>(hid, ln2, xh);
    // 7) fused up|gate projection + silu -> h1 (half, N/2 out)
    gemm_f16<2><<<dim3(2 * IDIM / BN, SLEN / BM), 256, GEMM_SMEM>>>(xh, wh + W_UP,
                                                                    nullptr, h1h,
                                                                    SLEN, 2 * IDIM, HDIM);
    // 8) down projection + residual -> output (fp32)
    gemm_f16<0><<<dim3(HDIM / BN, SLEN / BM), 256, GEMM_SMEM>>>(h1h, wh + W_DOWN,
                                                                hid, out,
                                                                SLEN, HDIM, IDIM);
}